// round 10
// baseline (speedup 1.0000x reference)
#include <cuda_runtime.h>

// FactorizedSpectralConv2d: x[32,64,128,128] f32, w0/w1[64,64,32,2] f32.
// out[b,o,m,n] = irfft_n( trunc32(rfft_n(x)) @ w0 ) + irfft_m( trunc32(rfft_m(x)) @ w1 )
// Implemented as 3 dense GEMM stages per branch with f-planar intermediate
// layouts so every global access is contiguous.

#define SQI 0.08838834764831843f   // 1/sqrt(128)

// ---- device-global scratch (allocation-free rule) ----
__device__ float g_Ffwd[128 * 64];        // [k][2f|2f+1]  fwd DFT basis (incl 1/sqrt(128))
__device__ float g_Finv[64 * 128];        // [s][n]        inv basis (incl 1/sqrt(128), x2 for f>=1, 0 for Im DC)
__device__ float g_w0re[32 * 64 * 64];    // [f][i][o]
__device__ float g_w0im[32 * 64 * 64];
__device__ float g_w1re[32 * 64 * 64];
__device__ float g_w1im[32 * 64 * 64];
__device__ float g_Xf[64 * 32 * 64 * 128]; // [s][b][i][m|n]  67 MB
__device__ float g_Yp[64 * 32 * 64 * 128]; // [s][b][o][m|n]  67 MB

// ---------------------------------------------------------------------------
// K0: build DFT bases + transpose weights to [f][i][o] planes.
// idx ranges: [0,8192) Ffwd, [8192,16384) Finv, [16384, 16384+4*131072) weights
__global__ __launch_bounds__(256) void k_init(const float* __restrict__ w0,
                                              const float* __restrict__ w1) {
    int idx = blockIdx.x * 256 + threadIdx.x;
    if (idx < 8192) {
        int k = idx >> 6, s = idx & 63;
        int f = s >> 1, c = s & 1;
        int t = (f * k) & 127;
        float sp, cp;
        sincospif((float)t * (1.0f / 64.0f), &sp, &cp);   // angle = 2*pi*t/128
        g_Ffwd[idx] = c ? (-SQI * sp) : (SQI * cp);
    } else if (idx < 16384) {
        int j = idx - 8192;
        int s = j >> 7, n = j & 127;
        int f = s >> 1, c = s & 1;
        int t = (f * n) & 127;
        float sp, cp;
        sincospif((float)t * (1.0f / 64.0f), &sp, &cp);
        float cf = (f == 0) ? SQI : (2.0f * SQI);          // DC unpaired; others x2
        g_Finv[j] = c ? (-cf * sp) : (cf * cp);            // f=0,c=1 -> sin(0)=0: Im(DC) ignored
    } else if (idx < 16384 + 4 * 131072) {
        int q = idx - 16384;
        int sel = q >> 17;           // 0:w0re 1:w0im 2:w1re 3:w1im
        int r = q & 131071;          // r = f*4096 + i*64 + o
        int f = r >> 12, i = (r >> 6) & 63, o = r & 63;
        const float* w = (sel >= 2) ? w1 : w0;
        float v = w[((i * 64 + o) * 32 + f) * 2 + (sel & 1)];
        if (sel == 0) g_w0re[r] = v;
        else if (sel == 1) g_w0im[r] = v;
        else if (sel == 2) g_w1re[r] = v;
        else g_w1im[r] = v;
    }
}

// ---------------------------------------------------------------------------
// K1a: forward DFT along last axis. Block = one (b,i): [128m x 128k] @ [128k x 64s].
// Output staged through smem -> planar g_Xf[s][b][i][m] with contiguous 512B rows.
__global__ __launch_bounds__(256) void k_fwd_y(const float* __restrict__ x) {
    extern __shared__ float sm[];
    float* As = sm;            // [128][36]  x tile (row-major m,k)
    float* Bs = sm + 4608;     // [32][64]   Ffwd chunk
    float* Ts = sm;            // [64][132]  output staging (reuses As/Bs after sync)

    int tid = threadIdx.x;
    int tx = tid & 15, ty = tid >> 4;
    int bi = blockIdx.x;
    const float* xr = x + (size_t)bi * 16384;

    float acc[8][4] = {};
    for (int kc = 0; kc < 4; ++kc) {
#pragma unroll
        for (int l = 0; l < 4; ++l) {                      // 128x32 floats
            int v = tid + l * 256;
            int row = v >> 3, kk = (v & 7) << 2;
            *(float4*)(As + row * 36 + kk) =
                *(const float4*)(xr + row * 128 + kc * 32 + kk);
        }
#pragma unroll
        for (int l = 0; l < 2; ++l) {                      // 32x64 floats
            int v = tid + l * 256;
            int kr = v >> 4, s4 = (v & 15) << 2;
            *(float4*)(Bs + kr * 64 + s4) =
                *(const float4*)(g_Ffwd + (kc * 32 + kr) * 64 + s4);
        }
        __syncthreads();
#pragma unroll 8
        for (int k = 0; k < 32; ++k) {
            float a[8];
#pragma unroll
            for (int j = 0; j < 8; ++j) a[j] = As[(ty * 8 + j) * 36 + k];
            float4 b4 = *(float4*)(Bs + k * 64 + tx * 4);
            float bb[4] = {b4.x, b4.y, b4.z, b4.w};
#pragma unroll
            for (int j = 0; j < 8; ++j)
#pragma unroll
                for (int c = 0; c < 4; ++c) acc[j][c] += a[j] * bb[c];
        }
        __syncthreads();
    }
#pragma unroll
    for (int j = 0; j < 8; ++j)
#pragma unroll
        for (int c = 0; c < 4; ++c)
            Ts[(tx * 4 + c) * 132 + ty * 8 + j] = acc[j][c];
    __syncthreads();
#pragma unroll
    for (int l = 0; l < 8; ++l) {                          // 64 rows of 128 floats
        int v = tid + l * 256;
        int s = v >> 5, m4 = (v & 31) << 2;
        *(float4*)(g_Xf + (s * 2048 + bi) * 128 + m4) = *(float4*)(Ts + s * 132 + m4);
    }
}

// K1b: forward DFT along axis -2 (contract over m). Block = one (b,i):
// T[n][s] = sum_m x[m][n] * Ffwd[m][s].
__global__ __launch_bounds__(256) void k_fwd_x(const float* __restrict__ x) {
    extern __shared__ float sm[];
    float* As = sm;            // [32][132]  x chunk (k=m rows, n cols)
    float* Bs = sm + 4224;     // [32][64]
    float* Ts = sm;            // [64][132]

    int tid = threadIdx.x;
    int tx = tid & 15, ty = tid >> 4;
    int bi = blockIdx.x;
    const float* xr = x + (size_t)bi * 16384;

    float acc[8][4] = {};
    for (int kc = 0; kc < 4; ++kc) {
#pragma unroll
        for (int l = 0; l < 4; ++l) {                      // 32x128 floats
            int v = tid + l * 256;
            int kr = v >> 5, n4 = (v & 31) << 2;
            *(float4*)(As + kr * 132 + n4) =
                *(const float4*)(xr + (kc * 32 + kr) * 128 + n4);
        }
#pragma unroll
        for (int l = 0; l < 2; ++l) {
            int v = tid + l * 256;
            int kr = v >> 4, s4 = (v & 15) << 2;
            *(float4*)(Bs + kr * 64 + s4) =
                *(const float4*)(g_Ffwd + (kc * 32 + kr) * 64 + s4);
        }
        __syncthreads();
#pragma unroll 8
        for (int k = 0; k < 32; ++k) {
            float a[8];
#pragma unroll
            for (int j = 0; j < 8; ++j) a[j] = As[k * 132 + ty * 8 + j];
            float4 b4 = *(float4*)(Bs + k * 64 + tx * 4);
            float bb[4] = {b4.x, b4.y, b4.z, b4.w};
#pragma unroll
            for (int j = 0; j < 8; ++j)
#pragma unroll
                for (int c = 0; c < 4; ++c) acc[j][c] += a[j] * bb[c];
        }
        __syncthreads();
    }
#pragma unroll
    for (int j = 0; j < 8; ++j)
#pragma unroll
        for (int c = 0; c < 4; ++c)
            Ts[(tx * 4 + c) * 132 + ty * 8 + j] = acc[j][c];
    __syncthreads();
#pragma unroll
    for (int l = 0; l < 8; ++l) {
        int v = tid + l * 256;
        int s = v >> 5, n4 = (v & 31) << 2;
        *(float4*)(g_Xf + (s * 2048 + bi) * 128 + n4) = *(float4*)(Ts + s * 132 + n4);
    }
}

// ---------------------------------------------------------------------------
// K2: per-mode complex channel mix. Block = (f, b, m-half):
//   Y[o][m] = sum_i conj-free complex mult: (Xr + iXi)(wre + i wim)
// Weights are L2-resident planar [f][i][o].
__global__ __launch_bounds__(256) void k_mix(int branch) {
    extern __shared__ float sm[];
    float* Wr = sm;                 // [64][68]
    float* Wi = sm + 64 * 68;
    float* Xr = sm + 2 * 64 * 68;   // [64 i][64 m]
    float* Xi = sm + 3 * 64 * 68;

    int tid = threadIdx.x;
    int bx = blockIdx.x;
    int f = bx >> 6;
    int b = (bx >> 1) & 31;
    int mh = bx & 1;

    const float* wpr = (branch ? g_w1re : g_w0re) + f * 4096;
    const float* wpi = (branch ? g_w1im : g_w0im) + f * 4096;
    int xbase = ((2 * f) * 2048 + b * 64) * 128 + mh * 64;   // + i*128

#pragma unroll
    for (int l = 0; l < 4; ++l) {
        int v = tid + l * 256;
        int i = v >> 4, c4 = (v & 15) << 2;
        *(float4*)(Wr + i * 68 + c4) = *(const float4*)(wpr + i * 64 + c4);
        *(float4*)(Wi + i * 68 + c4) = *(const float4*)(wpi + i * 64 + c4);
        *(float4*)(Xr + i * 68 + c4) = *(const float4*)(g_Xf + xbase + i * 128 + c4);
        *(float4*)(Xi + i * 68 + c4) = *(const float4*)(g_Xf + xbase + 262144 + i * 128 + c4);
    }
    __syncthreads();

    int ot = tid & 7, mt = tid >> 3;
    int m2 = mt * 2;
    float yr0[8] = {}, yr1[8] = {}, yi0[8] = {}, yi1[8] = {};
#pragma unroll 4
    for (int i = 0; i < 64; ++i) {
        float xr0 = Xr[i * 68 + m2], xr1 = Xr[i * 68 + m2 + 1];
        float xm0 = Xi[i * 68 + m2], xm1 = Xi[i * 68 + m2 + 1];
        float4 wa = *(float4*)(Wr + i * 68 + ot * 8);
        float4 wb = *(float4*)(Wr + i * 68 + ot * 8 + 4);
        float4 va = *(float4*)(Wi + i * 68 + ot * 8);
        float4 vb = *(float4*)(Wi + i * 68 + ot * 8 + 4);
        float wr8[8] = {wa.x, wa.y, wa.z, wa.w, wb.x, wb.y, wb.z, wb.w};
        float wi8[8] = {va.x, va.y, va.z, va.w, vb.x, vb.y, vb.z, vb.w};
#pragma unroll
        for (int oo = 0; oo < 8; ++oo) {
            yr0[oo] += wr8[oo] * xr0 - wi8[oo] * xm0;
            yr1[oo] += wr8[oo] * xr1 - wi8[oo] * xm1;
            yi0[oo] += wr8[oo] * xm0 + wi8[oo] * xr0;
            yi1[oo] += wr8[oo] * xm1 + wi8[oo] * xr1;
        }
    }
    int mg = mh * 64 + m2;
    int ybase = ((2 * f) * 32 + b) * 64;
#pragma unroll
    for (int oo = 0; oo < 8; ++oo) {
        int o = ot * 8 + oo;
        float* pr = g_Yp + (ybase + o) * 128 + mg;
        *(float2*)pr = make_float2(yr0[oo], yr1[oo]);
        *(float2*)(pr + 262144) = make_float2(yi0[oo], yi1[oo]);  // Im plane (s+1)
    }
}

// ---------------------------------------------------------------------------
// K3: inverse DFT. Block = one (b,o): out tile [128m x 128n], K = 64 spectral.
// branch 0 (width):  A = Y[s][m],    B = Finv[s][n]  -> write
// branch 1 (height): A = Finv[s][m], B = Y[s][n]     -> accumulate (+=)
// (operand-role swap makes m the row index in both -> coalesced epilogue)
__global__ __launch_bounds__(256) void k_inv(float* __restrict__ out, int branch) {
    extern __shared__ float sm[];
    float* As = sm;            // [64][132]
    float* Bs = sm + 64 * 132;

    int tid = threadIdx.x;
    int bo = blockIdx.x;
#pragma unroll
    for (int l = 0; l < 8; ++l) {
        int v = tid + l * 256;
        int s = v >> 5, c4 = (v & 31) << 2;
        float4 ya = *(const float4*)(g_Yp + (s * 2048 + bo) * 128 + c4);
        float4 fa = *(const float4*)(g_Finv + s * 128 + c4);
        if (branch == 0) {
            *(float4*)(As + s * 132 + c4) = ya;
            *(float4*)(Bs + s * 132 + c4) = fa;
        } else {
            *(float4*)(As + s * 132 + c4) = fa;
            *(float4*)(Bs + s * 132 + c4) = ya;
        }
    }
    __syncthreads();

    int tx = tid & 15, ty = tid >> 4;
    int n0 = tx * 8, m0 = ty * 8;
    float acc[8][8] = {};
#pragma unroll 4
    for (int s = 0; s < 64; ++s) {
        float4 a0 = *(float4*)(As + s * 132 + m0);
        float4 a1 = *(float4*)(As + s * 132 + m0 + 4);
        float4 b0 = *(float4*)(Bs + s * 132 + n0);
        float4 b1 = *(float4*)(Bs + s * 132 + n0 + 4);
        float av[8] = {a0.x, a0.y, a0.z, a0.w, a1.x, a1.y, a1.z, a1.w};
        float bv[8] = {b0.x, b0.y, b0.z, b0.w, b1.x, b1.y, b1.z, b1.w};
#pragma unroll
        for (int j = 0; j < 8; ++j)
#pragma unroll
            for (int c = 0; c < 8; ++c) acc[j][c] += av[j] * bv[c];
    }

    float* op = out + (size_t)bo * 16384;
    if (branch == 0) {
#pragma unroll
        for (int j = 0; j < 8; ++j) {
            *(float4*)(op + (m0 + j) * 128 + n0) =
                make_float4(acc[j][0], acc[j][1], acc[j][2], acc[j][3]);
            *(float4*)(op + (m0 + j) * 128 + n0 + 4) =
                make_float4(acc[j][4], acc[j][5], acc[j][6], acc[j][7]);
        }
    } else {
#pragma unroll
        for (int j = 0; j < 8; ++j) {
            float4 t0 = *(float4*)(op + (m0 + j) * 128 + n0);
            float4 t1 = *(float4*)(op + (m0 + j) * 128 + n0 + 4);
            t0.x += acc[j][0]; t0.y += acc[j][1]; t0.z += acc[j][2]; t0.w += acc[j][3];
            t1.x += acc[j][4]; t1.y += acc[j][5]; t1.z += acc[j][6]; t1.w += acc[j][7];
            *(float4*)(op + (m0 + j) * 128 + n0) = t0;
            *(float4*)(op + (m0 + j) * 128 + n0 + 4) = t1;
        }
    }
}

// ---------------------------------------------------------------------------
extern "C" void kernel_launch(void* const* d_in, const int* in_sizes, int n_in,
                              void* d_out, int out_size) {
    const float* x  = (const float*)d_in[0];
    const float* w0 = (const float*)d_in[1];
    const float* w1 = (const float*)d_in[2];
    float* out = (float*)d_out;

    (void)in_sizes; (void)n_in; (void)out_size;

    // >48KB dynamic smem opt-in (host-side calls, not captured as graph nodes)
    cudaFuncSetAttribute(k_mix, cudaFuncAttributeMaxDynamicSharedMemorySize, 4 * 64 * 68 * 4);
    cudaFuncSetAttribute(k_inv, cudaFuncAttributeMaxDynamicSharedMemorySize, 2 * 64 * 132 * 4);

    k_init<<<2112, 256>>>(w0, w1);

    // ---- branch Y (width / last axis), writes out ----
    k_fwd_y<<<2048, 256, 8448 * 4>>>(x);
    k_mix<<<2048, 256, 4 * 64 * 68 * 4>>>(0);
    k_inv<<<2048, 256, 2 * 64 * 132 * 4>>>(out, 0);

    // ---- branch X (height / axis -2), accumulates into out ----
    k_fwd_x<<<2048, 256, 8448 * 4>>>(x);
    k_mix<<<2048, 256, 4 * 64 * 68 * 4>>>(1);
    k_inv<<<2048, 256, 2 * 64 * 132 * 4>>>(out, 1);
}

// round 11
// speedup vs baseline: 1.0495x; 1.0495x over previous
#include <cuda_runtime.h>

// FactorizedSpectralConv2d: x[32,64,128,128] f32, w0/w1[64,64,32,2] f32.
// out = irfft_n(trunc32(rfft_n(x)) @ w0) + irfft_m(trunc32(rfft_m(x)) @ w1)
// Dense-GEMM formulation with real-DFT even/odd symmetry: forward and inverse
// DFT stages do half the MACs of the dense version.

#define SQI 0.08838834764831843f   // 1/sqrt(128)

// ---- device-global scratch ----
__device__ float g_cF[64 * 32];           // [k][f]  SQI*cos(2pi f k/128)
__device__ float g_sF[64 * 32];           // [k][f] -SQI*sin(2pi f k/128)
__device__ float g_pF[32];                // SQI*(-1)^f
__device__ float g_cI[32 * 64];           // [f][n]  cf*cos(2pi f n/128), cf=SQI(f=0)/2SQI
__device__ float g_sI[32 * 64];           // [f][n] -cf*sin(2pi f n/128)
__device__ float g_pI[32];                // cf*(-1)^f
__device__ float g_w0re[32 * 64 * 64];    // [f][i][o]
__device__ float g_w0im[32 * 64 * 64];
__device__ float g_w1re[32 * 64 * 64];
__device__ float g_w1im[32 * 64 * 64];
__device__ float g_Xf[64 * 32 * 64 * 128]; // [s][b][i][m|n]
__device__ float g_Yp[64 * 32 * 64 * 128]; // [s][b][o][m|n]

// ---------------------------------------------------------------------------
// K0: build symmetric DFT bases + transpose weights to [f][i][o] planes.
__global__ __launch_bounds__(256) void k_init(const float* __restrict__ w0,
                                              const float* __restrict__ w1) {
    int idx = blockIdx.x * 256 + threadIdx.x;
    if (idx < 2048) {                    // cF: k=idx>>5, f=idx&31
        int k = idx >> 5, f = idx & 31;
        int t = (f * k) & 127;
        g_cF[idx] = SQI * cospif((float)t * (1.0f / 64.0f));
    } else if (idx < 4096) {             // sF
        int q = idx - 2048;
        int k = q >> 5, f = q & 31;
        int t = (f * k) & 127;
        g_sF[q] = -SQI * sinpif((float)t * (1.0f / 64.0f));
    } else if (idx < 6144) {             // cI: f=q>>6, n=q&63
        int q = idx - 4096;
        int f = q >> 6, n = q & 63;
        int t = (f * n) & 127;
        float cf = (f == 0) ? SQI : (2.0f * SQI);
        g_cI[q] = cf * cospif((float)t * (1.0f / 64.0f));
    } else if (idx < 8192) {             // sI
        int q = idx - 6144;
        int f = q >> 6, n = q & 63;
        int t = (f * n) & 127;
        float cf = (f == 0) ? SQI : (2.0f * SQI);
        g_sI[q] = -cf * sinpif((float)t * (1.0f / 64.0f));
    } else if (idx < 8224) {             // pF
        int f = idx - 8192;
        g_pF[f] = (f & 1) ? -SQI : SQI;
    } else if (idx < 8256) {             // pI
        int f = idx - 8224;
        float cf = (f == 0) ? SQI : (2.0f * SQI);
        g_pI[f] = (f & 1) ? -cf : cf;
    } else if (idx < 8256 + 4 * 131072) { // weights
        int q = idx - 8256;
        int sel = q >> 17;
        int r = q & 131071;              // r = f*4096 + i*64 + o
        int f = r >> 12, i = (r >> 6) & 63, o = r & 63;
        const float* w = (sel >= 2) ? w1 : w0;
        float v = w[((i * 64 + o) * 32 + f) * 2 + (sel & 1)];
        if (sel == 0) g_w0re[r] = v;
        else if (sel == 1) g_w0im[r] = v;
        else if (sel == 2) g_w1re[r] = v;
        else g_w1im[r] = v;
    }
}

// ---------------------------------------------------------------------------
// K1a: forward DFT along last axis (contract over n=k) with symmetry.
// Block = one (b,i). In-place column fold, then two half-K GEMMs.
__global__ __launch_bounds__(128) void k_fwd_y(const float* __restrict__ x) {
    extern __shared__ float sm[];
    float* X  = sm;            // [128][132], col 128 zero-padded
    float* Cb = sm + 16896;    // [64][32]
    float* Sb = Cb + 2048;
    float* Pb = Sb + 2048;     // [32]

    int tid = threadIdx.x, bi = blockIdx.x;
    const float* xr = x + (size_t)bi * 16384;
#pragma unroll
    for (int l = 0; l < 32; ++l) {
        int v = tid + l * 128;
        int row = v >> 5, c4 = (v & 31) << 2;
        *(float4*)(X + row * 132 + c4) = *(const float4*)(xr + row * 128 + c4);
    }
    *(float4*)(X + tid * 132 + 128) = make_float4(0.f, 0.f, 0.f, 0.f);
#pragma unroll
    for (int l = 0; l < 16; ++l) {
        int v = tid + l * 128;
        Cb[v] = g_cF[v]; Sb[v] = g_sF[v];
    }
    if (tid < 32) Pb[tid] = g_pF[tid];
    __syncthreads();

    // in-place fold: cols 0..63 -> xe, cols 65..128 -> xo (col 64 = x[64])
    for (int v = tid; v < 8192; v += 128) {
        int row = v >> 6, k = v & 63;
        float* p = X + row * 132;
        float u = p[k], w = p[128 - k];
        p[k] = u + w; p[128 - k] = u - w;
    }
    __syncthreads();

    // thread map: f0 = tx*8 (tx=tid&3); m(j) = 32*w + 8*j + ty (conflict-free banks)
    int tx = tid & 3, ty = (tid >> 2) & 7, w = tid >> 5;
    int f0 = tx * 8;
    int mrow[4];
#pragma unroll
    for (int j = 0; j < 4; ++j) mrow[j] = 32 * w + 8 * j + ty;

    float ar[4][8] = {}, ai[4][8] = {};
#pragma unroll 2
    for (int k = 0; k < 64; ++k) {
        float xe[4], xo[4];
#pragma unroll
        for (int j = 0; j < 4; ++j) {
            xe[j] = X[mrow[j] * 132 + k];
            xo[j] = X[mrow[j] * 132 + 128 - k];
        }
        float4 ca = *(float4*)(Cb + k * 32 + f0), cb = *(float4*)(Cb + k * 32 + f0 + 4);
        float4 sa = *(float4*)(Sb + k * 32 + f0), sb = *(float4*)(Sb + k * 32 + f0 + 4);
        float cc[8] = {ca.x, ca.y, ca.z, ca.w, cb.x, cb.y, cb.z, cb.w};
        float ss[8] = {sa.x, sa.y, sa.z, sa.w, sb.x, sb.y, sb.z, sb.w};
#pragma unroll
        for (int j = 0; j < 4; ++j)
#pragma unroll
            for (int c = 0; c < 8; ++c) {
                ar[j][c] += xe[j] * cc[c];
                ai[j][c] += xo[j] * ss[c];
            }
    }
    // x[64] parity correction (Re only)
    {
        float pv[8];
#pragma unroll
        for (int c = 0; c < 8; ++c) pv[c] = Pb[f0 + c];
#pragma unroll
        for (int j = 0; j < 4; ++j) {
            float x64 = X[mrow[j] * 132 + 64];
#pragma unroll
            for (int c = 0; c < 8; ++c) ar[j][c] += x64 * pv[c];
        }
    }
#pragma unroll
    for (int c = 0; c < 8; ++c) {
        int f = f0 + c;
        float* pr = g_Xf + ((size_t)(2 * f) * 2048 + bi) * 128;
        float* pi = g_Xf + ((size_t)(2 * f + 1) * 2048 + bi) * 128;
#pragma unroll
        for (int j = 0; j < 4; ++j) {
            pr[mrow[j]] = ar[j][c];
            pi[mrow[j]] = ai[j][c];
        }
    }
}

// K1b: forward DFT along axis -2 (contract over m=k) with symmetry.
__global__ __launch_bounds__(128) void k_fwd_x(const float* __restrict__ x) {
    extern __shared__ float sm[];
    float* X  = sm;            // [129][132], row 128 zeroed
    float* Cb = sm + 17028;    // [64][32]
    float* Sb = Cb + 2048;
    float* Pb = Sb + 2048;

    int tid = threadIdx.x, bi = blockIdx.x;
    const float* xr = x + (size_t)bi * 16384;
#pragma unroll
    for (int l = 0; l < 32; ++l) {
        int v = tid + l * 128;
        int row = v >> 5, c4 = (v & 31) << 2;
        *(float4*)(X + row * 132 + c4) = *(const float4*)(xr + row * 128 + c4);
    }
    if (tid < 32) *(float4*)(X + 128 * 132 + tid * 4) = make_float4(0.f, 0.f, 0.f, 0.f);
#pragma unroll
    for (int l = 0; l < 16; ++l) {
        int v = tid + l * 128;
        Cb[v] = g_cF[v]; Sb[v] = g_sF[v];
    }
    if (tid < 32) Pb[tid] = g_pF[tid];
    __syncthreads();

    // in-place row fold: rows 0..63 -> xe, rows 65..128 -> xo (row 64 = x[64])
    for (int v = tid; v < 2048; v += 128) {
        int k = v >> 5, c4 = (v & 31) << 2;
        float4 u = *(float4*)(X + k * 132 + c4);
        float4 w = *(float4*)(X + (128 - k) * 132 + c4);
        *(float4*)(X + k * 132 + c4) =
            make_float4(u.x + w.x, u.y + w.y, u.z + w.z, u.w + w.w);
        *(float4*)(X + (128 - k) * 132 + c4) =
            make_float4(u.x - w.x, u.y - w.y, u.z - w.z, u.w - w.w);
    }
    __syncthreads();

    int tx = tid & 15, ty = tid >> 4;    // n0 = tx*8, f0 = ty*4
    int n0 = tx * 8, f0 = ty * 4;
    float ar[4][8] = {}, ai[4][8] = {};
#pragma unroll 2
    for (int k = 0; k < 64; ++k) {
        float4 e0 = *(float4*)(X + k * 132 + n0);
        float4 e1 = *(float4*)(X + k * 132 + n0 + 4);
        float4 o0 = *(float4*)(X + (128 - k) * 132 + n0);
        float4 o1 = *(float4*)(X + (128 - k) * 132 + n0 + 4);
        float xe[8] = {e0.x, e0.y, e0.z, e0.w, e1.x, e1.y, e1.z, e1.w};
        float xo[8] = {o0.x, o0.y, o0.z, o0.w, o1.x, o1.y, o1.z, o1.w};
        float cc[4], ss[4];
#pragma unroll
        for (int ff = 0; ff < 4; ++ff) {
            cc[ff] = Cb[k * 32 + f0 + ff];
            ss[ff] = Sb[k * 32 + f0 + ff];
        }
#pragma unroll
        for (int ff = 0; ff < 4; ++ff)
#pragma unroll
            for (int c = 0; c < 8; ++c) {
                ar[ff][c] += cc[ff] * xe[c];
                ai[ff][c] += ss[ff] * xo[c];
            }
    }
    {
        float4 h0 = *(float4*)(X + 64 * 132 + n0);
        float4 h1 = *(float4*)(X + 64 * 132 + n0 + 4);
        float xh[8] = {h0.x, h0.y, h0.z, h0.w, h1.x, h1.y, h1.z, h1.w};
#pragma unroll
        for (int ff = 0; ff < 4; ++ff) {
            float pv = Pb[f0 + ff];
#pragma unroll
            for (int c = 0; c < 8; ++c) ar[ff][c] += pv * xh[c];
        }
    }
#pragma unroll
    for (int ff = 0; ff < 4; ++ff) {
        int f = f0 + ff;
        float* pr = g_Xf + ((size_t)(2 * f) * 2048 + bi) * 128 + n0;
        float* pi = g_Xf + ((size_t)(2 * f + 1) * 2048 + bi) * 128 + n0;
        *(float4*)pr       = make_float4(ar[ff][0], ar[ff][1], ar[ff][2], ar[ff][3]);
        *(float4*)(pr + 4) = make_float4(ar[ff][4], ar[ff][5], ar[ff][6], ar[ff][7]);
        *(float4*)pi       = make_float4(ai[ff][0], ai[ff][1], ai[ff][2], ai[ff][3]);
        *(float4*)(pi + 4) = make_float4(ai[ff][4], ai[ff][5], ai[ff][6], ai[ff][7]);
    }
}

// ---------------------------------------------------------------------------
// K2: per-mode complex channel mix (unchanged). Block = (f, b, m-half).
__global__ __launch_bounds__(256) void k_mix(int branch) {
    extern __shared__ float sm[];
    float* Wr = sm;                 // [64][68]
    float* Wi = sm + 64 * 68;
    float* Xr = sm + 2 * 64 * 68;
    float* Xi = sm + 3 * 64 * 68;

    int tid = threadIdx.x;
    int bx = blockIdx.x;
    int f = bx >> 6;
    int b = (bx >> 1) & 31;
    int mh = bx & 1;

    const float* wpr = (branch ? g_w1re : g_w0re) + f * 4096;
    const float* wpi = (branch ? g_w1im : g_w0im) + f * 4096;
    int xbase = ((2 * f) * 2048 + b * 64) * 128 + mh * 64;

#pragma unroll
    for (int l = 0; l < 4; ++l) {
        int v = tid + l * 256;
        int i = v >> 4, c4 = (v & 15) << 2;
        *(float4*)(Wr + i * 68 + c4) = *(const float4*)(wpr + i * 64 + c4);
        *(float4*)(Wi + i * 68 + c4) = *(const float4*)(wpi + i * 64 + c4);
        *(float4*)(Xr + i * 68 + c4) = *(const float4*)(g_Xf + xbase + i * 128 + c4);
        *(float4*)(Xi + i * 68 + c4) = *(const float4*)(g_Xf + xbase + 262144 + i * 128 + c4);
    }
    __syncthreads();

    int ot = tid & 7, mt = tid >> 3;
    int m2 = mt * 2;
    float yr0[8] = {}, yr1[8] = {}, yi0[8] = {}, yi1[8] = {};
#pragma unroll 4
    for (int i = 0; i < 64; ++i) {
        float xr0 = Xr[i * 68 + m2], xr1 = Xr[i * 68 + m2 + 1];
        float xm0 = Xi[i * 68 + m2], xm1 = Xi[i * 68 + m2 + 1];
        float4 wa = *(float4*)(Wr + i * 68 + ot * 8);
        float4 wb = *(float4*)(Wr + i * 68 + ot * 8 + 4);
        float4 va = *(float4*)(Wi + i * 68 + ot * 8);
        float4 vb = *(float4*)(Wi + i * 68 + ot * 8 + 4);
        float wr8[8] = {wa.x, wa.y, wa.z, wa.w, wb.x, wb.y, wb.z, wb.w};
        float wi8[8] = {va.x, va.y, va.z, va.w, vb.x, vb.y, vb.z, vb.w};
#pragma unroll
        for (int oo = 0; oo < 8; ++oo) {
            yr0[oo] += wr8[oo] * xr0 - wi8[oo] * xm0;
            yr1[oo] += wr8[oo] * xr1 - wi8[oo] * xm1;
            yi0[oo] += wr8[oo] * xm0 + wi8[oo] * xr0;
            yi1[oo] += wr8[oo] * xm1 + wi8[oo] * xr1;
        }
    }
    int mg = mh * 64 + m2;
    int ybase = ((2 * f) * 32 + b) * 64;
#pragma unroll
    for (int oo = 0; oo < 8; ++oo) {
        int o = ot * 8 + oo;
        float* pr = g_Yp + (ybase + o) * 128 + mg;
        *(float2*)pr = make_float2(yr0[oo], yr1[oo]);
        *(float2*)(pr + 262144) = make_float2(yi0[oo], yi1[oo]);
    }
}

// ---------------------------------------------------------------------------
// K3a: inverse DFT, width branch (writes out). Block = one (b,o).
// c[m][n] = sum_f a_f[m] cI[f][n]; s[m][n] = sum_f b_f[m] sI[f][n]; n=0..63.
// out[m][n]=c+s, out[m][128-n]=c-s, out[m][64]=sum_f a_f par[f].
__global__ __launch_bounds__(256) void k_inv0(float* __restrict__ out) {
    extern __shared__ float sm[];
    float* As = sm;            // [64][132]
    float* Ci = sm + 8448;     // [32][64]
    float* Si = Ci + 2048;
    float* Pi = Si + 2048;     // [32]

    int tid = threadIdx.x, bo = blockIdx.x;
#pragma unroll
    for (int l = 0; l < 8; ++l) {
        int v = tid + l * 256;
        int s = v >> 5, c4 = (v & 31) << 2;
        *(float4*)(As + s * 132 + c4) =
            *(const float4*)(g_Yp + ((size_t)s * 2048 + bo) * 128 + c4);
    }
#pragma unroll
    for (int l = 0; l < 8; ++l) {
        int v = tid + l * 256;
        Ci[v] = g_cI[v]; Si[v] = g_sI[v];
    }
    if (tid < 32) Pi[tid] = g_pI[tid];
    __syncthreads();

    int tx = tid & 15, ty = tid >> 4;
    int n0 = tx * 4, m0 = ty * 8;
    float ac[8][4] = {}, as_[8][4] = {}, ae[8] = {};
#pragma unroll 4
    for (int f = 0; f < 32; ++f) {
        float4 a0 = *(float4*)(As + (2 * f) * 132 + m0);
        float4 a1 = *(float4*)(As + (2 * f) * 132 + m0 + 4);
        float4 b0 = *(float4*)(As + (2 * f + 1) * 132 + m0);
        float4 b1 = *(float4*)(As + (2 * f + 1) * 132 + m0 + 4);
        float av[8] = {a0.x, a0.y, a0.z, a0.w, a1.x, a1.y, a1.z, a1.w};
        float bv[8] = {b0.x, b0.y, b0.z, b0.w, b1.x, b1.y, b1.z, b1.w};
        float4 c4 = *(float4*)(Ci + f * 64 + n0);
        float4 s4 = *(float4*)(Si + f * 64 + n0);
        float cb[4] = {c4.x, c4.y, c4.z, c4.w};
        float sb[4] = {s4.x, s4.y, s4.z, s4.w};
        float pf = Pi[f];
#pragma unroll
        for (int j = 0; j < 8; ++j) {
#pragma unroll
            for (int c = 0; c < 4; ++c) {
                ac[j][c]  += av[j] * cb[c];
                as_[j][c] += bv[j] * sb[c];
            }
            ae[j] += av[j] * pf;
        }
    }
    float* op = out + (size_t)bo * 16384;
#pragma unroll
    for (int j = 0; j < 8; ++j) {
        int m = m0 + j;
        *(float4*)(op + m * 128 + n0) =
            make_float4(ac[j][0] + as_[j][0], ac[j][1] + as_[j][1],
                        ac[j][2] + as_[j][2], ac[j][3] + as_[j][3]);
#pragma unroll
        for (int c = 0; c < 4; ++c) {
            int n = n0 + c;
            if (n > 0) op[m * 128 + 128 - n] = ac[j][c] - as_[j][c];
        }
        if (tx == 0) op[m * 128 + 64] = ae[j];
    }
}

// K3b: inverse DFT, height branch (accumulates into out). Block = one (b,o).
// c[m][n] = sum_f cI[f][m] a_f[n]; rows mirrored -> coalesced float4 epilogue.
__global__ __launch_bounds__(256) void k_inv1(float* __restrict__ out) {
    extern __shared__ float sm[];
    float* As = sm;            // [64][132]
    float* Ci = sm + 8448;
    float* Si = Ci + 2048;
    float* Pi = Si + 2048;

    int tid = threadIdx.x, bo = blockIdx.x;
#pragma unroll
    for (int l = 0; l < 8; ++l) {
        int v = tid + l * 256;
        int s = v >> 5, c4 = (v & 31) << 2;
        *(float4*)(As + s * 132 + c4) =
            *(const float4*)(g_Yp + ((size_t)s * 2048 + bo) * 128 + c4);
    }
#pragma unroll
    for (int l = 0; l < 8; ++l) {
        int v = tid + l * 256;
        Ci[v] = g_cI[v]; Si[v] = g_sI[v];
    }
    if (tid < 32) Pi[tid] = g_pI[tid];
    __syncthreads();

    int tx = tid & 15, ty = tid >> 4;
    int n0 = tx * 8, m0 = ty * 4;
    float ac[4][8] = {}, as_[4][8] = {}, ae[8] = {};
#pragma unroll 4
    for (int f = 0; f < 32; ++f) {
        float4 a0 = *(float4*)(As + (2 * f) * 132 + n0);
        float4 a1 = *(float4*)(As + (2 * f) * 132 + n0 + 4);
        float4 b0 = *(float4*)(As + (2 * f + 1) * 132 + n0);
        float4 b1 = *(float4*)(As + (2 * f + 1) * 132 + n0 + 4);
        float av[8] = {a0.x, a0.y, a0.z, a0.w, a1.x, a1.y, a1.z, a1.w};
        float bv[8] = {b0.x, b0.y, b0.z, b0.w, b1.x, b1.y, b1.z, b1.w};
        float cc[4], ss[4];
#pragma unroll
        for (int j = 0; j < 4; ++j) {
            cc[j] = Ci[f * 64 + m0 + j];
            ss[j] = Si[f * 64 + m0 + j];
        }
        float pf = Pi[f];
#pragma unroll
        for (int j = 0; j < 4; ++j)
#pragma unroll
            for (int c = 0; c < 8; ++c) {
                ac[j][c]  += cc[j] * av[c];
                as_[j][c] += ss[j] * bv[c];
            }
#pragma unroll
        for (int c = 0; c < 8; ++c) ae[c] += av[c] * pf;
    }
    float* op = out + (size_t)bo * 16384;
#pragma unroll
    for (int j = 0; j < 4; ++j) {
        int m = m0 + j;
        {   // row m: += c+s
            float4 t0 = *(float4*)(op + m * 128 + n0);
            float4 t1 = *(float4*)(op + m * 128 + n0 + 4);
            t0.x += ac[j][0] + as_[j][0]; t0.y += ac[j][1] + as_[j][1];
            t0.z += ac[j][2] + as_[j][2]; t0.w += ac[j][3] + as_[j][3];
            t1.x += ac[j][4] + as_[j][4]; t1.y += ac[j][5] + as_[j][5];
            t1.z += ac[j][6] + as_[j][6]; t1.w += ac[j][7] + as_[j][7];
            *(float4*)(op + m * 128 + n0) = t0;
            *(float4*)(op + m * 128 + n0 + 4) = t1;
        }
        if (m > 0) {  // row 128-m: += c-s
            float4 t0 = *(float4*)(op + (128 - m) * 128 + n0);
            float4 t1 = *(float4*)(op + (128 - m) * 128 + n0 + 4);
            t0.x += ac[j][0] - as_[j][0]; t0.y += ac[j][1] - as_[j][1];
            t0.z += ac[j][2] - as_[j][2]; t0.w += ac[j][3] - as_[j][3];
            t1.x += ac[j][4] - as_[j][4]; t1.y += ac[j][5] - as_[j][5];
            t1.z += ac[j][6] - as_[j][6]; t1.w += ac[j][7] - as_[j][7];
            *(float4*)(op + (128 - m) * 128 + n0) = t0;
            *(float4*)(op + (128 - m) * 128 + n0 + 4) = t1;
        }
    }
    if (ty == 0) {  // row 64: += ae  (ae identical across ty)
        float4 t0 = *(float4*)(op + 64 * 128 + n0);
        float4 t1 = *(float4*)(op + 64 * 128 + n0 + 4);
        t0.x += ae[0]; t0.y += ae[1]; t0.z += ae[2]; t0.w += ae[3];
        t1.x += ae[4]; t1.y += ae[5]; t1.z += ae[6]; t1.w += ae[7];
        *(float4*)(op + 64 * 128 + n0) = t0;
        *(float4*)(op + 64 * 128 + n0 + 4) = t1;
    }
}

// ---------------------------------------------------------------------------
extern "C" void kernel_launch(void* const* d_in, const int* in_sizes, int n_in,
                              void* d_out, int out_size) {
    const float* x  = (const float*)d_in[0];
    const float* w0 = (const float*)d_in[1];
    const float* w1 = (const float*)d_in[2];
    float* out = (float*)d_out;
    (void)in_sizes; (void)n_in; (void)out_size;

    const int SMEM_FY  = (16896 + 2 * 2048 + 32) * 4;   // 84096
    const int SMEM_FX  = (17028 + 2 * 2048 + 32) * 4;   // 84624
    const int SMEM_MIX = 4 * 64 * 68 * 4;               // 69632
    const int SMEM_INV = (8448 + 2 * 2048 + 32) * 4;    // 50304

    cudaFuncSetAttribute(k_fwd_y, cudaFuncAttributeMaxDynamicSharedMemorySize, SMEM_FY);
    cudaFuncSetAttribute(k_fwd_x, cudaFuncAttributeMaxDynamicSharedMemorySize, SMEM_FX);
    cudaFuncSetAttribute(k_mix,   cudaFuncAttributeMaxDynamicSharedMemorySize, SMEM_MIX);
    cudaFuncSetAttribute(k_inv0,  cudaFuncAttributeMaxDynamicSharedMemorySize, SMEM_INV);
    cudaFuncSetAttribute(k_inv1,  cudaFuncAttributeMaxDynamicSharedMemorySize, SMEM_INV);

    k_init<<<2081, 256>>>(w0, w1);

    // branch Y (width): writes out
    k_fwd_y<<<2048, 128, SMEM_FY>>>(x);
    k_mix<<<2048, 256, SMEM_MIX>>>(0);
    k_inv0<<<2048, 256, SMEM_INV>>>(out);

    // branch X (height): accumulates into out
    k_fwd_x<<<2048, 128, SMEM_FX>>>(x);
    k_mix<<<2048, 256, SMEM_MIX>>>(1);
    k_inv1<<<2048, 256, SMEM_INV>>>(out);
}

// round 12
// speedup vs baseline: 1.2215x; 1.1639x over previous
#include <cuda_runtime.h>

// FactorizedSpectralConv2d: x[32,64,128,128] f32, w0/w1[64,64,32,2] f32.
// out = irfft_n(trunc32(rfft_n(x)) @ w0) + irfft_m(trunc32(rfft_m(x)) @ w1)
// Dense-GEMM formulation with real-DFT even/odd symmetry (half-K DFT stages),
// fused dual-branch forward transform, single dual-branch mix launch.

#define SQI 0.08838834764831843f   // 1/sqrt(128)

// ---- device-global scratch ----
__device__ float g_cF[64 * 32];           // [k][f]  SQI*cos(2pi f k/128)
__device__ float g_sF[64 * 32];           // [k][f] -SQI*sin(2pi f k/128)
__device__ float g_pF[32];                // SQI*(-1)^f
__device__ float g_cI[32 * 64];           // [f][n]  cf*cos, cf=SQI(f=0)/2SQI
__device__ float g_sI[32 * 64];           // [f][n] -cf*sin
__device__ float g_pI[32];                // cf*(-1)^f
__device__ float g_w0re[32 * 64 * 64];    // [f][i][o]
__device__ float g_w0im[32 * 64 * 64];
__device__ float g_w1re[32 * 64 * 64];
__device__ float g_w1im[32 * 64 * 64];
__device__ float g_Xf [64 * 32 * 64 * 128]; // branch Y spectra [s][b][i][m]
__device__ float g_Xf2[64 * 32 * 64 * 128]; // branch X spectra [s][b][i][n]
__device__ float g_Yp [64 * 32 * 64 * 128]; // branch Y mixed   [s][b][o][m]
__device__ float g_Yp2[64 * 32 * 64 * 128]; // branch X mixed   [s][b][o][n]

// ---------------------------------------------------------------------------
// K0: build symmetric DFT bases + transpose weights to [f][i][o] planes.
__global__ __launch_bounds__(256) void k_init(const float* __restrict__ w0,
                                              const float* __restrict__ w1) {
    int idx = blockIdx.x * 256 + threadIdx.x;
    if (idx < 2048) {                    // cF
        int k = idx >> 5, f = idx & 31;
        int t = (f * k) & 127;
        g_cF[idx] = SQI * cospif((float)t * (1.0f / 64.0f));
    } else if (idx < 4096) {             // sF
        int q = idx - 2048;
        int k = q >> 5, f = q & 31;
        int t = (f * k) & 127;
        g_sF[q] = -SQI * sinpif((float)t * (1.0f / 64.0f));
    } else if (idx < 6144) {             // cI
        int q = idx - 4096;
        int f = q >> 6, n = q & 63;
        int t = (f * n) & 127;
        float cf = (f == 0) ? SQI : (2.0f * SQI);
        g_cI[q] = cf * cospif((float)t * (1.0f / 64.0f));
    } else if (idx < 8192) {             // sI
        int q = idx - 6144;
        int f = q >> 6, n = q & 63;
        int t = (f * n) & 127;
        float cf = (f == 0) ? SQI : (2.0f * SQI);
        g_sI[q] = -cf * sinpif((float)t * (1.0f / 64.0f));
    } else if (idx < 8224) {             // pF
        int f = idx - 8192;
        g_pF[f] = (f & 1) ? -SQI : SQI;
    } else if (idx < 8256) {             // pI
        int f = idx - 8224;
        float cf = (f == 0) ? SQI : (2.0f * SQI);
        g_pI[f] = (f & 1) ? -cf : cf;
    } else if (idx < 8256 + 4 * 131072) { // weights
        int q = idx - 8256;
        int sel = q >> 17;
        int r = q & 131071;              // r = f*4096 + i*64 + o
        int f = r >> 12, i = (r >> 6) & 63, o = r & 63;
        const float* w = (sel >= 2) ? w1 : w0;
        float v = w[((i * 64 + o) * 32 + f) * 2 + (sel & 1)];
        if (sel == 0) g_w0re[r] = v;
        else if (sel == 1) g_w0im[r] = v;
        else if (sel == 2) g_w1re[r] = v;
        else g_w1im[r] = v;
    }
}

// ---------------------------------------------------------------------------
// K1: fused forward DFT, both branches. Block = one (b,i), 256 threads.
// Load x tile once. Branch Y (contract over n): on-the-fly even/odd fold.
// Then in-place row fold feeds branch X (contract over m).
__global__ __launch_bounds__(256) void k_fwd(const float* __restrict__ x) {
    extern __shared__ float sm[];
    float* X  = sm;            // [129][132], col 128..131 and row 128 zeroed
    float* Cb = sm + 17028;    // [64][32]
    float* Sb = Cb + 2048;
    float* Pb = Sb + 2048;     // [32]

    int tid = threadIdx.x, bi = blockIdx.x;
    const float* xr = x + (size_t)bi * 16384;
#pragma unroll
    for (int l = 0; l < 16; ++l) {
        int v = tid + l * 256;
        int row = v >> 5, c4 = (v & 31) << 2;
        *(float4*)(X + row * 132 + c4) = *(const float4*)(xr + row * 128 + c4);
    }
    if (tid < 129) *(float4*)(X + tid * 132 + 128) = make_float4(0.f, 0.f, 0.f, 0.f);
    if (tid < 33)  *(float4*)(X + 128 * 132 + tid * 4) = make_float4(0.f, 0.f, 0.f, 0.f);
#pragma unroll
    for (int l = 0; l < 8; ++l) {
        int v = tid + l * 256;
        Cb[v] = g_cF[v]; Sb[v] = g_sF[v];
    }
    if (tid < 32) Pb[tid] = g_pF[tid];
    __syncthreads();

    // ---- branch Y: on-the-fly column fold ----
    {
        int tx = tid & 3, rest = tid >> 2;      // f0 = tx*8; rows rest, rest+64
        int f0 = tx * 8;
        float ar[2][8] = {}, ai[2][8] = {};
#pragma unroll 2
        for (int k = 0; k < 64; ++k) {
            float4 ca = *(float4*)(Cb + k * 32 + f0), cb = *(float4*)(Cb + k * 32 + f0 + 4);
            float4 sa = *(float4*)(Sb + k * 32 + f0), sb = *(float4*)(Sb + k * 32 + f0 + 4);
            float cc[8] = {ca.x, ca.y, ca.z, ca.w, cb.x, cb.y, cb.z, cb.w};
            float ss[8] = {sa.x, sa.y, sa.z, sa.w, sb.x, sb.y, sb.z, sb.w};
#pragma unroll
            for (int j = 0; j < 2; ++j) {
                int m = rest + 64 * j;
                float u = X[m * 132 + k], w = X[m * 132 + 128 - k];
                float xe = u + w, xo = u - w;
#pragma unroll
                for (int c = 0; c < 8; ++c) {
                    ar[j][c] += xe * cc[c];
                    ai[j][c] += xo * ss[c];
                }
            }
        }
        float pv[8];
#pragma unroll
        for (int c = 0; c < 8; ++c) pv[c] = Pb[f0 + c];
#pragma unroll
        for (int j = 0; j < 2; ++j) {
            float x64 = X[(rest + 64 * j) * 132 + 64];
#pragma unroll
            for (int c = 0; c < 8; ++c) ar[j][c] += x64 * pv[c];
        }
#pragma unroll
        for (int c = 0; c < 8; ++c) {
            int f = f0 + c;
            float* pr = g_Xf + ((size_t)(2 * f) * 2048 + bi) * 128;
            float* pi = g_Xf + ((size_t)(2 * f + 1) * 2048 + bi) * 128;
#pragma unroll
            for (int j = 0; j < 2; ++j) {
                int m = rest + 64 * j;
                pr[m] = ar[j][c];
                pi[m] = ai[j][c];
            }
        }
    }
    __syncthreads();

    // ---- in-place row fold (rows 0..63 += mirror; 65..128 = diff; 64 kept) ----
    for (int v = tid; v < 2048; v += 256) {
        int k = v >> 5, c4 = (v & 31) << 2;
        float4 u = *(float4*)(X + k * 132 + c4);
        float4 w = *(float4*)(X + (128 - k) * 132 + c4);
        *(float4*)(X + k * 132 + c4) =
            make_float4(u.x + w.x, u.y + w.y, u.z + w.z, u.w + w.w);
        *(float4*)(X + (128 - k) * 132 + c4) =
            make_float4(u.x - w.x, u.y - w.y, u.z - w.z, u.w - w.w);
    }
    __syncthreads();

    // ---- branch X: pre-folded rows ----
    {
        int tx = tid & 31, ty = tid >> 5;       // n0 = tx*4; f0 = ty*4
        int n0 = tx * 4, f0 = ty * 4;
        float ar[4][4] = {}, ai[4][4] = {};
#pragma unroll 2
        for (int k = 0; k < 64; ++k) {
            float4 e4 = *(float4*)(X + k * 132 + n0);
            float4 o4 = *(float4*)(X + (128 - k) * 132 + n0);
            float xe[4] = {e4.x, e4.y, e4.z, e4.w};
            float xo[4] = {o4.x, o4.y, o4.z, o4.w};
            float4 c4v = *(float4*)(Cb + k * 32 + f0);
            float4 s4v = *(float4*)(Sb + k * 32 + f0);
            float cc[4] = {c4v.x, c4v.y, c4v.z, c4v.w};
            float ssv[4] = {s4v.x, s4v.y, s4v.z, s4v.w};
#pragma unroll
            for (int ff = 0; ff < 4; ++ff)
#pragma unroll
                for (int c = 0; c < 4; ++c) {
                    ar[ff][c] += cc[ff] * xe[c];
                    ai[ff][c] += ssv[ff] * xo[c];
                }
        }
        {
            float4 h4 = *(float4*)(X + 64 * 132 + n0);
            float xh[4] = {h4.x, h4.y, h4.z, h4.w};
#pragma unroll
            for (int ff = 0; ff < 4; ++ff) {
                float pv = Pb[f0 + ff];
#pragma unroll
                for (int c = 0; c < 4; ++c) ar[ff][c] += pv * xh[c];
            }
        }
#pragma unroll
        for (int ff = 0; ff < 4; ++ff) {
            int f = f0 + ff;
            float* pr = g_Xf2 + ((size_t)(2 * f) * 2048 + bi) * 128 + n0;
            float* pi = g_Xf2 + ((size_t)(2 * f + 1) * 2048 + bi) * 128 + n0;
            *(float4*)pr = make_float4(ar[ff][0], ar[ff][1], ar[ff][2], ar[ff][3]);
            *(float4*)pi = make_float4(ai[ff][0], ai[ff][1], ai[ff][2], ai[ff][3]);
        }
    }
}

// ---------------------------------------------------------------------------
// K2: per-mode complex channel mix, both branches in one launch.
// Block = (branch, f, b), full m=128 tile. Thread: 8 o x 4 m complex.
__global__ __launch_bounds__(256) void k_mix() {
    extern __shared__ float sm[];
    float* Wr = sm;                 // [64][68]
    float* Wi = sm + 64 * 68;
    float* Xr = sm + 2 * 64 * 68;   // [64 i][132]
    float* Xi = Xr + 64 * 132;

    int tid = threadIdx.x;
    int bx = blockIdx.x;
    int branch = bx >> 10;
    int r = bx & 1023;
    int f = r >> 5, b = r & 31;

    const float* wpr = (branch ? g_w1re : g_w0re) + f * 4096;
    const float* wpi = (branch ? g_w1im : g_w0im) + f * 4096;
    const float* Xsrc = branch ? g_Xf2 : g_Xf;
    float* Ydst = branch ? g_Yp2 : g_Yp;
    size_t xbase = ((size_t)(2 * f) * 2048 + b * 64) * 128;

#pragma unroll
    for (int l = 0; l < 4; ++l) {
        int v = tid + l * 256;
        int i = v >> 4, c4 = (v & 15) << 2;
        *(float4*)(Wr + i * 68 + c4) = *(const float4*)(wpr + i * 64 + c4);
        *(float4*)(Wi + i * 68 + c4) = *(const float4*)(wpi + i * 64 + c4);
    }
#pragma unroll
    for (int l = 0; l < 8; ++l) {
        int v = tid + l * 256;
        int i = v >> 5, c4 = (v & 31) << 2;
        *(float4*)(Xr + i * 132 + c4) = *(const float4*)(Xsrc + xbase + i * 128 + c4);
        *(float4*)(Xi + i * 132 + c4) = *(const float4*)(Xsrc + xbase + 262144 + i * 128 + c4);
    }
    __syncthreads();

    int ot = tid & 7, mt = tid >> 3;
    int o0 = ot * 8, m0 = mt * 4;
    float yr[8][4] = {}, yi[8][4] = {};
#pragma unroll 4
    for (int i = 0; i < 64; ++i) {
        float4 xr4 = *(float4*)(Xr + i * 132 + m0);
        float4 xi4 = *(float4*)(Xi + i * 132 + m0);
        float xrv[4] = {xr4.x, xr4.y, xr4.z, xr4.w};
        float xiv[4] = {xi4.x, xi4.y, xi4.z, xi4.w};
        float4 wa = *(float4*)(Wr + i * 68 + o0);
        float4 wb = *(float4*)(Wr + i * 68 + o0 + 4);
        float4 va = *(float4*)(Wi + i * 68 + o0);
        float4 vb = *(float4*)(Wi + i * 68 + o0 + 4);
        float wr8[8] = {wa.x, wa.y, wa.z, wa.w, wb.x, wb.y, wb.z, wb.w};
        float wi8[8] = {va.x, va.y, va.z, va.w, vb.x, vb.y, vb.z, vb.w};
#pragma unroll
        for (int oo = 0; oo < 8; ++oo)
#pragma unroll
            for (int mm = 0; mm < 4; ++mm) {
                yr[oo][mm] += wr8[oo] * xrv[mm] - wi8[oo] * xiv[mm];
                yi[oo][mm] += wr8[oo] * xiv[mm] + wi8[oo] * xrv[mm];
            }
    }
    size_t ybase = ((size_t)(2 * f) * 32 + b) * 64;
#pragma unroll
    for (int oo = 0; oo < 8; ++oo) {
        int o = o0 + oo;
        float* pr = Ydst + (ybase + o) * 128 + m0;
        *(float4*)pr = make_float4(yr[oo][0], yr[oo][1], yr[oo][2], yr[oo][3]);
        *(float4*)(pr + 262144) = make_float4(yi[oo][0], yi[oo][1], yi[oo][2], yi[oo][3]);
    }
}

// ---------------------------------------------------------------------------
// K3a: inverse DFT, width branch (writes out). Block = one (b,o).
__global__ __launch_bounds__(256) void k_inv0(float* __restrict__ out) {
    extern __shared__ float sm[];
    float* As = sm;            // [64][132]
    float* Ci = sm + 8448;     // [32][64]
    float* Si = Ci + 2048;
    float* Pi = Si + 2048;

    int tid = threadIdx.x, bo = blockIdx.x;
#pragma unroll
    for (int l = 0; l < 8; ++l) {
        int v = tid + l * 256;
        int s = v >> 5, c4 = (v & 31) << 2;
        *(float4*)(As + s * 132 + c4) =
            *(const float4*)(g_Yp + ((size_t)s * 2048 + bo) * 128 + c4);
    }
#pragma unroll
    for (int l = 0; l < 8; ++l) {
        int v = tid + l * 256;
        Ci[v] = g_cI[v]; Si[v] = g_sI[v];
    }
    if (tid < 32) Pi[tid] = g_pI[tid];
    __syncthreads();

    int tx = tid & 15, ty = tid >> 4;
    int n0 = tx * 4, m0 = ty * 8;
    float ac[8][4] = {}, as_[8][4] = {}, ae[8] = {};
#pragma unroll 4
    for (int f = 0; f < 32; ++f) {
        float4 a0 = *(float4*)(As + (2 * f) * 132 + m0);
        float4 a1 = *(float4*)(As + (2 * f) * 132 + m0 + 4);
        float4 b0 = *(float4*)(As + (2 * f + 1) * 132 + m0);
        float4 b1 = *(float4*)(As + (2 * f + 1) * 132 + m0 + 4);
        float av[8] = {a0.x, a0.y, a0.z, a0.w, a1.x, a1.y, a1.z, a1.w};
        float bv[8] = {b0.x, b0.y, b0.z, b0.w, b1.x, b1.y, b1.z, b1.w};
        float4 c4 = *(float4*)(Ci + f * 64 + n0);
        float4 s4 = *(float4*)(Si + f * 64 + n0);
        float cb[4] = {c4.x, c4.y, c4.z, c4.w};
        float sb[4] = {s4.x, s4.y, s4.z, s4.w};
        float pf = Pi[f];
#pragma unroll
        for (int j = 0; j < 8; ++j) {
#pragma unroll
            for (int c = 0; c < 4; ++c) {
                ac[j][c]  += av[j] * cb[c];
                as_[j][c] += bv[j] * sb[c];
            }
            ae[j] += av[j] * pf;
        }
    }
    float* op = out + (size_t)bo * 16384;
#pragma unroll
    for (int j = 0; j < 8; ++j) {
        int m = m0 + j;
        *(float4*)(op + m * 128 + n0) =
            make_float4(ac[j][0] + as_[j][0], ac[j][1] + as_[j][1],
                        ac[j][2] + as_[j][2], ac[j][3] + as_[j][3]);
#pragma unroll
        for (int c = 0; c < 4; ++c) {
            int n = n0 + c;
            if (n > 0) op[m * 128 + 128 - n] = ac[j][c] - as_[j][c];
        }
        if (tx == 0) op[m * 128 + 64] = ae[j];
    }
}

// K3b: inverse DFT, height branch (accumulates into out). Block = one (b,o).
__global__ __launch_bounds__(256) void k_inv1(float* __restrict__ out) {
    extern __shared__ float sm[];
    float* As = sm;            // [64][132]
    float* Ci = sm + 8448;
    float* Si = Ci + 2048;
    float* Pi = Si + 2048;

    int tid = threadIdx.x, bo = blockIdx.x;
#pragma unroll
    for (int l = 0; l < 8; ++l) {
        int v = tid + l * 256;
        int s = v >> 5, c4 = (v & 31) << 2;
        *(float4*)(As + s * 132 + c4) =
            *(const float4*)(g_Yp2 + ((size_t)s * 2048 + bo) * 128 + c4);
    }
#pragma unroll
    for (int l = 0; l < 8; ++l) {
        int v = tid + l * 256;
        Ci[v] = g_cI[v]; Si[v] = g_sI[v];
    }
    if (tid < 32) Pi[tid] = g_pI[tid];
    __syncthreads();

    int tx = tid & 15, ty = tid >> 4;
    int n0 = tx * 8, m0 = ty * 4;
    float ac[4][8] = {}, as_[4][8] = {}, ae[8] = {};
#pragma unroll 4
    for (int f = 0; f < 32; ++f) {
        float4 a0 = *(float4*)(As + (2 * f) * 132 + n0);
        float4 a1 = *(float4*)(As + (2 * f) * 132 + n0 + 4);
        float4 b0 = *(float4*)(As + (2 * f + 1) * 132 + n0);
        float4 b1 = *(float4*)(As + (2 * f + 1) * 132 + n0 + 4);
        float av[8] = {a0.x, a0.y, a0.z, a0.w, a1.x, a1.y, a1.z, a1.w};
        float bv[8] = {b0.x, b0.y, b0.z, b0.w, b1.x, b1.y, b1.z, b1.w};
        float cc[4], ss[4];
#pragma unroll
        for (int j = 0; j < 4; ++j) {
            cc[j] = Ci[f * 64 + m0 + j];
            ss[j] = Si[f * 64 + m0 + j];
        }
        float pf = Pi[f];
#pragma unroll
        for (int j = 0; j < 4; ++j)
#pragma unroll
            for (int c = 0; c < 8; ++c) {
                ac[j][c]  += cc[j] * av[c];
                as_[j][c] += ss[j] * bv[c];
            }
#pragma unroll
        for (int c = 0; c < 8; ++c) ae[c] += av[c] * pf;
    }
    float* op = out + (size_t)bo * 16384;
#pragma unroll
    for (int j = 0; j < 4; ++j) {
        int m = m0 + j;
        {
            float4 t0 = *(float4*)(op + m * 128 + n0);
            float4 t1 = *(float4*)(op + m * 128 + n0 + 4);
            t0.x += ac[j][0] + as_[j][0]; t0.y += ac[j][1] + as_[j][1];
            t0.z += ac[j][2] + as_[j][2]; t0.w += ac[j][3] + as_[j][3];
            t1.x += ac[j][4] + as_[j][4]; t1.y += ac[j][5] + as_[j][5];
            t1.z += ac[j][6] + as_[j][6]; t1.w += ac[j][7] + as_[j][7];
            *(float4*)(op + m * 128 + n0) = t0;
            *(float4*)(op + m * 128 + n0 + 4) = t1;
        }
        if (m > 0) {
            float4 t0 = *(float4*)(op + (128 - m) * 128 + n0);
            float4 t1 = *(float4*)(op + (128 - m) * 128 + n0 + 4);
            t0.x += ac[j][0] - as_[j][0]; t0.y += ac[j][1] - as_[j][1];
            t0.z += ac[j][2] - as_[j][2]; t0.w += ac[j][3] - as_[j][3];
            t1.x += ac[j][4] - as_[j][4]; t1.y += ac[j][5] - as_[j][5];
            t1.z += ac[j][6] - as_[j][6]; t1.w += ac[j][7] - as_[j][7];
            *(float4*)(op + (128 - m) * 128 + n0) = t0;
            *(float4*)(op + (128 - m) * 128 + n0 + 4) = t1;
        }
    }
    if (ty == 0) {
        float4 t0 = *(float4*)(op + 64 * 128 + n0);
        float4 t1 = *(float4*)(op + 64 * 128 + n0 + 4);
        t0.x += ae[0]; t0.y += ae[1]; t0.z += ae[2]; t0.w += ae[3];
        t1.x += ae[4]; t1.y += ae[5]; t1.z += ae[6]; t1.w += ae[7];
        *(float4*)(op + 64 * 128 + n0) = t0;
        *(float4*)(op + 64 * 128 + n0 + 4) = t1;
    }
}

// ---------------------------------------------------------------------------
extern "C" void kernel_launch(void* const* d_in, const int* in_sizes, int n_in,
                              void* d_out, int out_size) {
    const float* x  = (const float*)d_in[0];
    const float* w0 = (const float*)d_in[1];
    const float* w1 = (const float*)d_in[2];
    float* out = (float*)d_out;
    (void)in_sizes; (void)n_in; (void)out_size;

    const int SMEM_FWD = (17028 + 2 * 2048 + 32) * 4;         // 84624
    const int SMEM_MIX = (2 * 64 * 68 + 2 * 64 * 132) * 4;    // 102400
    const int SMEM_INV = (8448 + 2 * 2048 + 32) * 4;          // 50304

    cudaFuncSetAttribute(k_fwd,  cudaFuncAttributeMaxDynamicSharedMemorySize, SMEM_FWD);
    cudaFuncSetAttribute(k_mix,  cudaFuncAttributeMaxDynamicSharedMemorySize, SMEM_MIX);
    cudaFuncSetAttribute(k_inv0, cudaFuncAttributeMaxDynamicSharedMemorySize, SMEM_INV);
    cudaFuncSetAttribute(k_inv1, cudaFuncAttributeMaxDynamicSharedMemorySize, SMEM_INV);

    k_init<<<2081, 256>>>(w0, w1);
    k_fwd <<<2048, 256, SMEM_FWD>>>(x);      // both branches' spectra
    k_mix <<<2048, 256, SMEM_MIX>>>();       // both branches' channel mix
    k_inv0<<<2048, 256, SMEM_INV>>>(out);    // width branch -> out
    k_inv1<<<2048, 256, SMEM_INV>>>(out);    // height branch += out
}

// round 13
// speedup vs baseline: 1.2680x; 1.0380x over previous
#include <cuda_runtime.h>

// FactorizedSpectralConv2d: x[32,64,128,128] f32, w0/w1[64,64,32,2] f32.
// out = irfft_n(trunc32(rfft_n(x)) @ w0) + irfft_m(trunc32(rfft_m(x)) @ w1)
// Dense-GEMM formulation with real-DFT even/odd symmetry (half-K DFT stages),
// fused dual-branch forward transform; mix/inv retiled for 3 CTAs/SM.

#define SQI 0.08838834764831843f   // 1/sqrt(128)

// ---- device-global scratch ----
__device__ float g_cF[64 * 32];           // [k][f]  SQI*cos(2pi f k/128)
__device__ float g_sF[64 * 32];           // [k][f] -SQI*sin(2pi f k/128)
__device__ float g_pF[32];                // SQI*(-1)^f
__device__ float g_cI[32 * 64];           // [f][n]  cf*cos, cf=SQI(f=0)/2SQI
__device__ float g_sI[32 * 64];           // [f][n] -cf*sin
__device__ float g_pI[32];                // cf*(-1)^f
__device__ float g_w0re[32 * 64 * 64];    // [f][i][o]
__device__ float g_w0im[32 * 64 * 64];
__device__ float g_w1re[32 * 64 * 64];
__device__ float g_w1im[32 * 64 * 64];
__device__ float g_Xf [64 * 32 * 64 * 128]; // branch Y spectra [s][b][i][m]
__device__ float g_Xf2[64 * 32 * 64 * 128]; // branch X spectra [s][b][i][n]
__device__ float g_Yp [64 * 32 * 64 * 128]; // branch Y mixed   [s][b][o][m]
__device__ float g_Yp2[64 * 32 * 64 * 128]; // branch X mixed   [s][b][o][n]

// ---------------------------------------------------------------------------
// K0: build symmetric DFT bases + transpose weights to [f][i][o] planes.
__global__ __launch_bounds__(256) void k_init(const float* __restrict__ w0,
                                              const float* __restrict__ w1) {
    int idx = blockIdx.x * 256 + threadIdx.x;
    if (idx < 2048) {                    // cF
        int k = idx >> 5, f = idx & 31;
        int t = (f * k) & 127;
        g_cF[idx] = SQI * cospif((float)t * (1.0f / 64.0f));
    } else if (idx < 4096) {             // sF
        int q = idx - 2048;
        int k = q >> 5, f = q & 31;
        int t = (f * k) & 127;
        g_sF[q] = -SQI * sinpif((float)t * (1.0f / 64.0f));
    } else if (idx < 6144) {             // cI
        int q = idx - 4096;
        int f = q >> 6, n = q & 63;
        int t = (f * n) & 127;
        float cf = (f == 0) ? SQI : (2.0f * SQI);
        g_cI[q] = cf * cospif((float)t * (1.0f / 64.0f));
    } else if (idx < 8192) {             // sI
        int q = idx - 6144;
        int f = q >> 6, n = q & 63;
        int t = (f * n) & 127;
        float cf = (f == 0) ? SQI : (2.0f * SQI);
        g_sI[q] = -cf * sinpif((float)t * (1.0f / 64.0f));
    } else if (idx < 8224) {             // pF
        int f = idx - 8192;
        g_pF[f] = (f & 1) ? -SQI : SQI;
    } else if (idx < 8256) {             // pI
        int f = idx - 8224;
        float cf = (f == 0) ? SQI : (2.0f * SQI);
        g_pI[f] = (f & 1) ? -cf : cf;
    } else if (idx < 8256 + 4 * 131072) { // weights
        int q = idx - 8256;
        int sel = q >> 17;
        int r = q & 131071;              // r = f*4096 + i*64 + o
        int f = r >> 12, i = (r >> 6) & 63, o = r & 63;
        const float* w = (sel >= 2) ? w1 : w0;
        float v = w[((i * 64 + o) * 32 + f) * 2 + (sel & 1)];
        if (sel == 0) g_w0re[r] = v;
        else if (sel == 1) g_w0im[r] = v;
        else if (sel == 2) g_w1re[r] = v;
        else g_w1im[r] = v;
    }
}

// ---------------------------------------------------------------------------
// K1: fused forward DFT, both branches. Block = one (b,i), 256 threads.
__global__ __launch_bounds__(256) void k_fwd(const float* __restrict__ x) {
    extern __shared__ float sm[];
    float* X  = sm;            // [129][132]
    float* Cb = sm + 17028;    // [64][32]
    float* Sb = Cb + 2048;
    float* Pb = Sb + 2048;     // [32]

    int tid = threadIdx.x, bi = blockIdx.x;
    const float* xr = x + (size_t)bi * 16384;
#pragma unroll
    for (int l = 0; l < 16; ++l) {
        int v = tid + l * 256;
        int row = v >> 5, c4 = (v & 31) << 2;
        *(float4*)(X + row * 132 + c4) = *(const float4*)(xr + row * 128 + c4);
    }
    if (tid < 129) *(float4*)(X + tid * 132 + 128) = make_float4(0.f, 0.f, 0.f, 0.f);
    if (tid < 33)  *(float4*)(X + 128 * 132 + tid * 4) = make_float4(0.f, 0.f, 0.f, 0.f);
#pragma unroll
    for (int l = 0; l < 8; ++l) {
        int v = tid + l * 256;
        Cb[v] = g_cF[v]; Sb[v] = g_sF[v];
    }
    if (tid < 32) Pb[tid] = g_pF[tid];
    __syncthreads();

    // ---- branch Y: on-the-fly column fold ----
    {
        int tx = tid & 3, rest = tid >> 2;
        int f0 = tx * 8;
        float ar[2][8] = {}, ai[2][8] = {};
#pragma unroll 2
        for (int k = 0; k < 64; ++k) {
            float4 ca = *(float4*)(Cb + k * 32 + f0), cb = *(float4*)(Cb + k * 32 + f0 + 4);
            float4 sa = *(float4*)(Sb + k * 32 + f0), sb = *(float4*)(Sb + k * 32 + f0 + 4);
            float cc[8] = {ca.x, ca.y, ca.z, ca.w, cb.x, cb.y, cb.z, cb.w};
            float ss[8] = {sa.x, sa.y, sa.z, sa.w, sb.x, sb.y, sb.z, sb.w};
#pragma unroll
            for (int j = 0; j < 2; ++j) {
                int m = rest + 64 * j;
                float u = X[m * 132 + k], w = X[m * 132 + 128 - k];
                float xe = u + w, xo = u - w;
#pragma unroll
                for (int c = 0; c < 8; ++c) {
                    ar[j][c] += xe * cc[c];
                    ai[j][c] += xo * ss[c];
                }
            }
        }
        float pv[8];
#pragma unroll
        for (int c = 0; c < 8; ++c) pv[c] = Pb[f0 + c];
#pragma unroll
        for (int j = 0; j < 2; ++j) {
            float x64 = X[(rest + 64 * j) * 132 + 64];
#pragma unroll
            for (int c = 0; c < 8; ++c) ar[j][c] += x64 * pv[c];
        }
#pragma unroll
        for (int c = 0; c < 8; ++c) {
            int f = f0 + c;
            float* pr = g_Xf + ((size_t)(2 * f) * 2048 + bi) * 128;
            float* pi = g_Xf + ((size_t)(2 * f + 1) * 2048 + bi) * 128;
#pragma unroll
            for (int j = 0; j < 2; ++j) {
                int m = rest + 64 * j;
                pr[m] = ar[j][c];
                pi[m] = ai[j][c];
            }
        }
    }
    __syncthreads();

    // ---- in-place row fold ----
    for (int v = tid; v < 2048; v += 256) {
        int k = v >> 5, c4 = (v & 31) << 2;
        float4 u = *(float4*)(X + k * 132 + c4);
        float4 w = *(float4*)(X + (128 - k) * 132 + c4);
        *(float4*)(X + k * 132 + c4) =
            make_float4(u.x + w.x, u.y + w.y, u.z + w.z, u.w + w.w);
        *(float4*)(X + (128 - k) * 132 + c4) =
            make_float4(u.x - w.x, u.y - w.y, u.z - w.z, u.w - w.w);
    }
    __syncthreads();

    // ---- branch X ----
    {
        int tx = tid & 31, ty = tid >> 5;
        int n0 = tx * 4, f0 = ty * 4;
        float ar[4][4] = {}, ai[4][4] = {};
#pragma unroll 2
        for (int k = 0; k < 64; ++k) {
            float4 e4 = *(float4*)(X + k * 132 + n0);
            float4 o4 = *(float4*)(X + (128 - k) * 132 + n0);
            float xe[4] = {e4.x, e4.y, e4.z, e4.w};
            float xo[4] = {o4.x, o4.y, o4.z, o4.w};
            float4 c4v = *(float4*)(Cb + k * 32 + f0);
            float4 s4v = *(float4*)(Sb + k * 32 + f0);
            float cc[4] = {c4v.x, c4v.y, c4v.z, c4v.w};
            float ssv[4] = {s4v.x, s4v.y, s4v.z, s4v.w};
#pragma unroll
            for (int ff = 0; ff < 4; ++ff)
#pragma unroll
                for (int c = 0; c < 4; ++c) {
                    ar[ff][c] += cc[ff] * xe[c];
                    ai[ff][c] += ssv[ff] * xo[c];
                }
        }
        {
            float4 h4 = *(float4*)(X + 64 * 132 + n0);
            float xh[4] = {h4.x, h4.y, h4.z, h4.w};
#pragma unroll
            for (int ff = 0; ff < 4; ++ff) {
                float pv = Pb[f0 + ff];
#pragma unroll
                for (int c = 0; c < 4; ++c) ar[ff][c] += pv * xh[c];
            }
        }
#pragma unroll
        for (int ff = 0; ff < 4; ++ff) {
            int f = f0 + ff;
            float* pr = g_Xf2 + ((size_t)(2 * f) * 2048 + bi) * 128 + n0;
            float* pi = g_Xf2 + ((size_t)(2 * f + 1) * 2048 + bi) * 128 + n0;
            *(float4*)pr = make_float4(ar[ff][0], ar[ff][1], ar[ff][2], ar[ff][3]);
            *(float4*)pi = make_float4(ai[ff][0], ai[ff][1], ai[ff][2], ai[ff][3]);
        }
    }
}

// ---------------------------------------------------------------------------
// K2: per-mode complex channel mix. Block = (branch, f, b, m-half), 64o x 64m.
// Thread: 4o x 4m complex (32 accs). 3 CTAs/SM.
__global__ __launch_bounds__(256, 3) void k_mix() {
    extern __shared__ float sm[];
    float* Wr = sm;                 // [64][68]
    float* Wi = Wr + 64 * 68;
    float* Xr = Wi + 64 * 68;       // [64 i][68] (64 m cols)
    float* Xi = Xr + 64 * 68;

    int tid = threadIdx.x;
    int bx = blockIdx.x;
    int branch = bx >> 11;
    int r = bx & 2047;
    int f = r >> 6, b = (r >> 1) & 31, mh = r & 1;

    const float* wpr = (branch ? g_w1re : g_w0re) + f * 4096;
    const float* wpi = (branch ? g_w1im : g_w0im) + f * 4096;
    const float* Xsrc = branch ? g_Xf2 : g_Xf;
    float* Ydst = branch ? g_Yp2 : g_Yp;
    size_t xbase = ((size_t)(2 * f) * 2048 + b * 64) * 128 + mh * 64;

#pragma unroll
    for (int l = 0; l < 4; ++l) {
        int v = tid + l * 256;
        int i = v >> 4, c4 = (v & 15) << 2;
        *(float4*)(Wr + i * 68 + c4) = *(const float4*)(wpr + i * 64 + c4);
        *(float4*)(Wi + i * 68 + c4) = *(const float4*)(wpi + i * 64 + c4);
        *(float4*)(Xr + i * 68 + c4) = *(const float4*)(Xsrc + xbase + i * 128 + c4);
        *(float4*)(Xi + i * 68 + c4) = *(const float4*)(Xsrc + xbase + 262144 + i * 128 + c4);
    }
    __syncthreads();

    int tx = tid & 15, ty = tid >> 4;
    int o0 = tx * 4, m0 = ty * 4;
    float yr[4][4] = {}, yi[4][4] = {};
#pragma unroll 4
    for (int i = 0; i < 64; ++i) {
        float4 xr4 = *(float4*)(Xr + i * 68 + m0);
        float4 xi4 = *(float4*)(Xi + i * 68 + m0);
        float4 wr4 = *(float4*)(Wr + i * 68 + o0);
        float4 wi4 = *(float4*)(Wi + i * 68 + o0);
        float xrv[4] = {xr4.x, xr4.y, xr4.z, xr4.w};
        float xiv[4] = {xi4.x, xi4.y, xi4.z, xi4.w};
        float wrv[4] = {wr4.x, wr4.y, wr4.z, wr4.w};
        float wiv[4] = {wi4.x, wi4.y, wi4.z, wi4.w};
#pragma unroll
        for (int oo = 0; oo < 4; ++oo)
#pragma unroll
            for (int mm = 0; mm < 4; ++mm) {
                yr[oo][mm] += wrv[oo] * xrv[mm] - wiv[oo] * xiv[mm];
                yi[oo][mm] += wrv[oo] * xiv[mm] + wiv[oo] * xrv[mm];
            }
    }
    size_t ybase = ((size_t)(2 * f) * 32 + b) * 64;
#pragma unroll
    for (int oo = 0; oo < 4; ++oo) {
        int o = o0 + oo;
        float* pr = Ydst + (ybase + o) * 128 + mh * 64 + m0;
        *(float4*)pr = make_float4(yr[oo][0], yr[oo][1], yr[oo][2], yr[oo][3]);
        *(float4*)(pr + 262144) = make_float4(yi[oo][0], yi[oo][1], yi[oo][2], yi[oo][3]);
    }
}

// ---------------------------------------------------------------------------
// K3a: inverse DFT, width branch (writes out). Block = (b*o, m-half): 64m x 128n.
__global__ __launch_bounds__(256, 3) void k_inv0(float* __restrict__ out) {
    extern __shared__ float sm[];
    float* As = sm;            // [64 s][68] (64 m cols)
    float* Ci = As + 64 * 68;  // [32][64]
    float* Si = Ci + 2048;
    float* Pi = Si + 2048;

    int tid = threadIdx.x;
    int bx = blockIdx.x;
    int bo = bx >> 1, mh = bx & 1;
#pragma unroll
    for (int l = 0; l < 4; ++l) {
        int v = tid + l * 256;
        int s = v >> 4, c4 = (v & 15) << 2;
        *(float4*)(As + s * 68 + c4) =
            *(const float4*)(g_Yp + ((size_t)s * 2048 + bo) * 128 + mh * 64 + c4);
    }
#pragma unroll
    for (int l = 0; l < 8; ++l) {
        int v = tid + l * 256;
        Ci[v] = g_cI[v]; Si[v] = g_sI[v];
    }
    if (tid < 32) Pi[tid] = g_pI[tid];
    __syncthreads();

    int tx = tid & 15, ty = tid >> 4;
    int n0 = tx * 4, m0l = ty * 4;
    float ac[4][4] = {}, as_[4][4] = {}, ae[4] = {};
#pragma unroll 4
    for (int f = 0; f < 32; ++f) {
        float4 a4 = *(float4*)(As + (2 * f) * 68 + m0l);
        float4 b4 = *(float4*)(As + (2 * f + 1) * 68 + m0l);
        float4 c4v = *(float4*)(Ci + f * 64 + n0);
        float4 s4v = *(float4*)(Si + f * 64 + n0);
        float av[4] = {a4.x, a4.y, a4.z, a4.w};
        float bv[4] = {b4.x, b4.y, b4.z, b4.w};
        float cb[4] = {c4v.x, c4v.y, c4v.z, c4v.w};
        float sb[4] = {s4v.x, s4v.y, s4v.z, s4v.w};
        float pf = Pi[f];
#pragma unroll
        for (int j = 0; j < 4; ++j) {
#pragma unroll
            for (int c = 0; c < 4; ++c) {
                ac[j][c]  += av[j] * cb[c];
                as_[j][c] += bv[j] * sb[c];
            }
            ae[j] += av[j] * pf;
        }
    }
    float* op = out + (size_t)bo * 16384;
#pragma unroll
    for (int j = 0; j < 4; ++j) {
        int m = mh * 64 + m0l + j;
        *(float4*)(op + m * 128 + n0) =
            make_float4(ac[j][0] + as_[j][0], ac[j][1] + as_[j][1],
                        ac[j][2] + as_[j][2], ac[j][3] + as_[j][3]);
#pragma unroll
        for (int c = 0; c < 4; ++c) {
            int n = n0 + c;
            if (n > 0) op[m * 128 + 128 - n] = ac[j][c] - as_[j][c];
        }
        if (tx == 0) op[m * 128 + 64] = ae[j];
    }
}

// K3b: inverse DFT, height branch (accumulates into out). Block = (b*o, n-half).
__global__ __launch_bounds__(256, 3) void k_inv1(float* __restrict__ out) {
    extern __shared__ float sm[];
    float* As = sm;            // [64 s][68] (64 n cols)
    float* Ci = As + 64 * 68;
    float* Si = Ci + 2048;
    float* Pi = Si + 2048;

    int tid = threadIdx.x;
    int bx = blockIdx.x;
    int bo = bx >> 1, nh = bx & 1;
#pragma unroll
    for (int l = 0; l < 4; ++l) {
        int v = tid + l * 256;
        int s = v >> 4, c4 = (v & 15) << 2;
        *(float4*)(As + s * 68 + c4) =
            *(const float4*)(g_Yp2 + ((size_t)s * 2048 + bo) * 128 + nh * 64 + c4);
    }
#pragma unroll
    for (int l = 0; l < 8; ++l) {
        int v = tid + l * 256;
        Ci[v] = g_cI[v]; Si[v] = g_sI[v];
    }
    if (tid < 32) Pi[tid] = g_pI[tid];
    __syncthreads();

    int tx = tid & 15, ty = tid >> 4;
    int n0l = tx * 4, m0 = ty * 4;
    float ac[4][4] = {}, as_[4][4] = {}, ae[4] = {};
#pragma unroll 4
    for (int f = 0; f < 32; ++f) {
        float4 a4 = *(float4*)(As + (2 * f) * 68 + n0l);
        float4 b4 = *(float4*)(As + (2 * f + 1) * 68 + n0l);
        float4 c4v = *(float4*)(Ci + f * 64 + m0);
        float4 s4v = *(float4*)(Si + f * 64 + m0);
        float av[4] = {a4.x, a4.y, a4.z, a4.w};
        float bv[4] = {b4.x, b4.y, b4.z, b4.w};
        float cc[4] = {c4v.x, c4v.y, c4v.z, c4v.w};
        float ss[4] = {s4v.x, s4v.y, s4v.z, s4v.w};
        float pf = Pi[f];
#pragma unroll
        for (int j = 0; j < 4; ++j)
#pragma unroll
            for (int c = 0; c < 4; ++c) {
                ac[j][c]  += cc[j] * av[c];
                as_[j][c] += ss[j] * bv[c];
            }
#pragma unroll
        for (int c = 0; c < 4; ++c) ae[c] += av[c] * pf;
    }
    float* op = out + (size_t)bo * 16384;
    int n0 = nh * 64 + n0l;
#pragma unroll
    for (int j = 0; j < 4; ++j) {
        int m = m0 + j;
        {
            float4 t = *(float4*)(op + m * 128 + n0);
            t.x += ac[j][0] + as_[j][0]; t.y += ac[j][1] + as_[j][1];
            t.z += ac[j][2] + as_[j][2]; t.w += ac[j][3] + as_[j][3];
            *(float4*)(op + m * 128 + n0) = t;
        }
        if (m > 0) {
            float4 t = *(float4*)(op + (128 - m) * 128 + n0);
            t.x += ac[j][0] - as_[j][0]; t.y += ac[j][1] - as_[j][1];
            t.z += ac[j][2] - as_[j][2]; t.w += ac[j][3] - as_[j][3];
            *(float4*)(op + (128 - m) * 128 + n0) = t;
        }
    }
    if (ty == 0) {
        float4 t = *(float4*)(op + 64 * 128 + n0);
        t.x += ae[0]; t.y += ae[1]; t.z += ae[2]; t.w += ae[3];
        *(float4*)(op + 64 * 128 + n0) = t;
    }
}

// ---------------------------------------------------------------------------
extern "C" void kernel_launch(void* const* d_in, const int* in_sizes, int n_in,
                              void* d_out, int out_size) {
    const float* x  = (const float*)d_in[0];
    const float* w0 = (const float*)d_in[1];
    const float* w1 = (const float*)d_in[2];
    float* out = (float*)d_out;
    (void)in_sizes; (void)n_in; (void)out_size;

    const int SMEM_FWD = (17028 + 2 * 2048 + 32) * 4;   // 84624
    const int SMEM_MIX = 4 * 64 * 68 * 4;               // 69632
    const int SMEM_INV = (64 * 68 + 2 * 2048 + 32) * 4; // 33920

    cudaFuncSetAttribute(k_fwd,  cudaFuncAttributeMaxDynamicSharedMemorySize, SMEM_FWD);
    cudaFuncSetAttribute(k_mix,  cudaFuncAttributeMaxDynamicSharedMemorySize, SMEM_MIX);
    cudaFuncSetAttribute(k_inv0, cudaFuncAttributeMaxDynamicSharedMemorySize, SMEM_INV);
    cudaFuncSetAttribute(k_inv1, cudaFuncAttributeMaxDynamicSharedMemorySize, SMEM_INV);

    k_init<<<2081, 256>>>(w0, w1);
    k_fwd <<<2048, 256, SMEM_FWD>>>(x);      // both branches' spectra
    k_mix <<<4096, 256, SMEM_MIX>>>();       // both branches' channel mix
    k_inv0<<<4096, 256, SMEM_INV>>>(out);    // width branch -> out
    k_inv1<<<4096, 256, SMEM_INV>>>(out);    // height branch += out
}

// round 16
// speedup vs baseline: 1.6342x; 1.2889x over previous
#include <cuda_runtime.h>
#include <cstdint>

// FactorizedSpectralConv2d: x[32,64,128,128] f32, w0/w1[64,64,32,2] f32.
// out = irfft_n(trunc32(rfft_n(x)) @ w0) + irfft_m(trunc32(rfft_m(x)) @ w1)
// DFT stages: SIMT fp32 with even/odd symmetry. Channel mix: tf32 mma.sync
// (arch-portable tensor path; tcgen05 is rejected by the harness toolchain).
// R16 fix: k_mix_mma grid is 1024 (bg3|mh1|f5|branch1), was wrongly 2048.

#define SQI 0.08838834764831843f   // 1/sqrt(128)

// ---- device-global scratch ----
__device__ float g_cF[64 * 32];           // [k][f]  SQI*cos
__device__ float g_sF[64 * 32];           // [k][f] -SQI*sin
__device__ float g_pF[32];                // SQI*(-1)^f
__device__ float g_cI[32 * 64];           // [f][n]  cf*cos
__device__ float g_sI[32 * 64];           // [f][n] -cf*sin
__device__ float g_pI[32];                // cf*(-1)^f
__device__ float g_Wmix[2 * 32 * 128 * 128]; // [branch][f][o2][i2] mix operand A
__device__ float g_Xf [64 * 32 * 64 * 128];  // branch Y spectra [s][b][i][m]
__device__ float g_Xf2[64 * 32 * 64 * 128];  // branch X spectra [s][b][i][n]
__device__ float g_Yp [64 * 32 * 64 * 128];  // branch Y mixed   [s][b][o][m]
__device__ float g_Yp2[64 * 32 * 64 * 128];  // branch X mixed   [s][b][o][n]

__device__ __forceinline__ uint32_t f2tf(float f) {
    uint32_t r;
    asm("cvt.rna.tf32.f32 %0, %1;" : "=r"(r) : "f"(f));
    return r;
}

__device__ __forceinline__ void mma_tf32(float* c, const uint32_t* a, const uint32_t* b) {
    asm volatile(
        "mma.sync.aligned.m16n8k8.row.col.f32.tf32.tf32.f32 "
        "{%0,%1,%2,%3}, {%4,%5,%6,%7}, {%8,%9}, {%0,%1,%2,%3};"
        : "+f"(c[0]), "+f"(c[1]), "+f"(c[2]), "+f"(c[3])
        : "r"(a[0]), "r"(a[1]), "r"(a[2]), "r"(a[3]), "r"(b[0]), "r"(b[1]));
}

// ---------------------------------------------------------------------------
// K0: DFT bases + mix operand A = [[Wr,-Wi],[Wi,Wr]] per (branch,f).
__global__ __launch_bounds__(256) void k_init(const float* __restrict__ w0,
                                              const float* __restrict__ w1) {
    int idx = blockIdx.x * 256 + threadIdx.x;
    if (idx < 2048) {                    // cF
        int k = idx >> 5, f = idx & 31;
        int t = (f * k) & 127;
        g_cF[idx] = SQI * cospif((float)t * (1.0f / 64.0f));
    } else if (idx < 4096) {             // sF
        int q = idx - 2048;
        int k = q >> 5, f = q & 31;
        int t = (f * k) & 127;
        g_sF[q] = -SQI * sinpif((float)t * (1.0f / 64.0f));
    } else if (idx < 6144) {             // cI
        int q = idx - 4096;
        int f = q >> 6, n = q & 63;
        int t = (f * n) & 127;
        float cf = (f == 0) ? SQI : (2.0f * SQI);
        g_cI[q] = cf * cospif((float)t * (1.0f / 64.0f));
    } else if (idx < 8192) {             // sI
        int q = idx - 6144;
        int f = q >> 6, n = q & 63;
        int t = (f * n) & 127;
        float cf = (f == 0) ? SQI : (2.0f * SQI);
        g_sI[q] = -cf * sinpif((float)t * (1.0f / 64.0f));
    } else if (idx < 8224) {             // pF
        int f = idx - 8192;
        g_pF[f] = (f & 1) ? -SQI : SQI;
    } else if (idx < 8256) {             // pI
        int f = idx - 8224;
        float cf = (f == 0) ? SQI : (2.0f * SQI);
        g_pI[f] = (f & 1) ? -cf : cf;
    } else if (idx < 8256 + 2 * 32 * 128 * 128) {  // g_Wmix
        int q = idx - 8256;
        int branch = q >> 19;
        int r = q & 524287;
        int f = r >> 14, o2 = (r >> 7) & 127, i2 = r & 127;
        int i = i2 & 63, o = o2 & 63;
        const float* w = branch ? w1 : w0;
        int base = ((i * 64 + o) * 32 + f) * 2;
        float v;
        if (o2 < 64)  v = (i2 < 64) ?  w[base + 0] : -w[base + 1];
        else          v = (i2 < 64) ?  w[base + 1] :  w[base + 0];
        g_Wmix[q] = v;
    }
}

// ---------------------------------------------------------------------------
// K1: fused forward DFT, both branches. Block = one (b,i), 256 threads.
__global__ __launch_bounds__(256) void k_fwd(const float* __restrict__ x) {
    extern __shared__ float sm[];
    float* X  = sm;            // [129][132]
    float* Cb = sm + 17028;    // [64][32]
    float* Sb = Cb + 2048;
    float* Pb = Sb + 2048;     // [32]

    int tid = threadIdx.x, bi = blockIdx.x;
    const float* xr = x + (size_t)bi * 16384;
#pragma unroll
    for (int l = 0; l < 16; ++l) {
        int v = tid + l * 256;
        int row = v >> 5, c4 = (v & 31) << 2;
        *(float4*)(X + row * 132 + c4) = *(const float4*)(xr + row * 128 + c4);
    }
    if (tid < 129) *(float4*)(X + tid * 132 + 128) = make_float4(0.f, 0.f, 0.f, 0.f);
    if (tid < 33)  *(float4*)(X + 128 * 132 + tid * 4) = make_float4(0.f, 0.f, 0.f, 0.f);
#pragma unroll
    for (int l = 0; l < 8; ++l) {
        int v = tid + l * 256;
        Cb[v] = g_cF[v]; Sb[v] = g_sF[v];
    }
    if (tid < 32) Pb[tid] = g_pF[tid];
    __syncthreads();

    // ---- branch Y: on-the-fly column fold ----
    {
        int tx = tid & 3, rest = tid >> 2;
        int f0 = tx * 8;
        float ar[2][8] = {}, ai[2][8] = {};
#pragma unroll 2
        for (int k = 0; k < 64; ++k) {
            float4 ca = *(float4*)(Cb + k * 32 + f0), cb = *(float4*)(Cb + k * 32 + f0 + 4);
            float4 sa = *(float4*)(Sb + k * 32 + f0), sb = *(float4*)(Sb + k * 32 + f0 + 4);
            float cc[8] = {ca.x, ca.y, ca.z, ca.w, cb.x, cb.y, cb.z, cb.w};
            float ss[8] = {sa.x, sa.y, sa.z, sa.w, sb.x, sb.y, sb.z, sb.w};
#pragma unroll
            for (int j = 0; j < 2; ++j) {
                int m = rest + 64 * j;
                float u = X[m * 132 + k], w = X[m * 132 + 128 - k];
                float xe = u + w, xo = u - w;
#pragma unroll
                for (int c = 0; c < 8; ++c) {
                    ar[j][c] += xe * cc[c];
                    ai[j][c] += xo * ss[c];
                }
            }
        }
        float pv[8];
#pragma unroll
        for (int c = 0; c < 8; ++c) pv[c] = Pb[f0 + c];
#pragma unroll
        for (int j = 0; j < 2; ++j) {
            float x64 = X[(rest + 64 * j) * 132 + 64];
#pragma unroll
            for (int c = 0; c < 8; ++c) ar[j][c] += x64 * pv[c];
        }
#pragma unroll
        for (int c = 0; c < 8; ++c) {
            int f = f0 + c;
            float* pr = g_Xf + ((size_t)(2 * f) * 2048 + bi) * 128;
            float* pi = g_Xf + ((size_t)(2 * f + 1) * 2048 + bi) * 128;
#pragma unroll
            for (int j = 0; j < 2; ++j) {
                int m = rest + 64 * j;
                pr[m] = ar[j][c];
                pi[m] = ai[j][c];
            }
        }
    }
    __syncthreads();

    // ---- in-place row fold ----
    for (int v = tid; v < 2048; v += 256) {
        int k = v >> 5, c4 = (v & 31) << 2;
        float4 u = *(float4*)(X + k * 132 + c4);
        float4 w = *(float4*)(X + (128 - k) * 132 + c4);
        *(float4*)(X + k * 132 + c4) =
            make_float4(u.x + w.x, u.y + w.y, u.z + w.z, u.w + w.w);
        *(float4*)(X + (128 - k) * 132 + c4) =
            make_float4(u.x - w.x, u.y - w.y, u.z - w.z, u.w - w.w);
    }
    __syncthreads();

    // ---- branch X ----
    {
        int tx = tid & 31, ty = tid >> 5;
        int n0 = tx * 4, f0 = ty * 4;
        float ar[4][4] = {}, ai[4][4] = {};
#pragma unroll 2
        for (int k = 0; k < 64; ++k) {
            float4 e4 = *(float4*)(X + k * 132 + n0);
            float4 o4 = *(float4*)(X + (128 - k) * 132 + n0);
            float xe[4] = {e4.x, e4.y, e4.z, e4.w};
            float xo[4] = {o4.x, o4.y, o4.z, o4.w};
            float4 c4v = *(float4*)(Cb + k * 32 + f0);
            float4 s4v = *(float4*)(Sb + k * 32 + f0);
            float cc[4] = {c4v.x, c4v.y, c4v.z, c4v.w};
            float ssv[4] = {s4v.x, s4v.y, s4v.z, s4v.w};
#pragma unroll
            for (int ff = 0; ff < 4; ++ff)
#pragma unroll
                for (int c = 0; c < 4; ++c) {
                    ar[ff][c] += cc[ff] * xe[c];
                    ai[ff][c] += ssv[ff] * xo[c];
                }
        }
        {
            float4 h4 = *(float4*)(X + 64 * 132 + n0);
            float xh[4] = {h4.x, h4.y, h4.z, h4.w};
#pragma unroll
            for (int ff = 0; ff < 4; ++ff) {
                float pv = Pb[f0 + ff];
#pragma unroll
                for (int c = 0; c < 4; ++c) ar[ff][c] += pv * xh[c];
            }
        }
#pragma unroll
        for (int ff = 0; ff < 4; ++ff) {
            int f = f0 + ff;
            float* pr = g_Xf2 + ((size_t)(2 * f) * 2048 + bi) * 128 + n0;
            float* pi = g_Xf2 + ((size_t)(2 * f + 1) * 2048 + bi) * 128 + n0;
            *(float4*)pr = make_float4(ar[ff][0], ar[ff][1], ar[ff][2], ar[ff][3]);
            *(float4*)pi = make_float4(ai[ff][0], ai[ff][1], ai[ff][2], ai[ff][3]);
        }
    }
}

// ---------------------------------------------------------------------------
// K2: channel mix on tf32 mma.sync.
// Block = (branch, f, mh, bg): A[128 o2][128 i2] in smem (tf32), loop 4 b.
// D[o2=128][m=64] = A x B,  B[i2=128][m=64] = [Xr;Xi] slab (tf32, col-frag).
// Warp tiling: 8 warps = 4 (o2) x 2 (m), each warp 32x32, K=128 in 16 k8 steps.
__global__ __launch_bounds__(256) void k_mix_mma() {
    extern __shared__ float smf[];
    uint32_t* As = (uint32_t*)smf;            // [128][132] tf32
    uint32_t* Bs = As + 128 * 132;            // [128][72]  tf32

    int tid = threadIdx.x;
    int bx = blockIdx.x;                      // 1024 blocks: bg3|mh1|f5|branch1
    int bg = bx & 7, mh = (bx >> 3) & 1, f = (bx >> 4) & 31, branch = bx >> 9;

    const float* Ap = g_Wmix + (((size_t)branch * 32 + f) << 14);
    const float* Xsrc = branch ? g_Xf2 : g_Xf;
    float* Ydst = branch ? g_Yp2 : g_Yp;

    // ---- A fill once (fp32 -> tf32) ----
#pragma unroll
    for (int l = 0; l < 16; ++l) {
        int v = tid + l * 256;
        int o2 = v >> 5, c4 = (v & 31) << 2;
        float4 d = *(const float4*)(Ap + o2 * 128 + c4);
        uint4 t = make_uint4(f2tf(d.x), f2tf(d.y), f2tf(d.z), f2tf(d.w));
        *(uint4*)(As + o2 * 132 + c4) = t;
    }

    int lane = tid & 31, wid = tid >> 5;
    int gid = lane >> 2, tig = lane & 3;
    int ot = (wid & 3) * 32;          // o2 tile base
    int nt = (wid >> 2) * 32;         // m tile base
    int plane = 2 * f + (ot >> 6);    // const per warp
    int obase = ot & 63;

    for (int bb = 0; bb < 4; ++bb) {
        int b = bg * 4 + bb;
        // ---- B fill (fp32 -> tf32) ----
        size_t xb = ((size_t)(2 * f) * 2048 + (size_t)b * 64) * 128 + mh * 64;
#pragma unroll
        for (int l = 0; l < 8; ++l) {
            int v = tid + l * 256;
            int i2 = v >> 4, c4 = (v & 15) << 2;
            const float* src = Xsrc + xb + (size_t)(i2 >> 6) * 262144 + (i2 & 63) * 128 + c4;
            float4 d = *(const float4*)src;
            uint4 t = make_uint4(f2tf(d.x), f2tf(d.y), f2tf(d.z), f2tf(d.w));
            *(uint4*)(Bs + i2 * 72 + c4) = t;
        }
        __syncthreads();

        float c[2][4][4];
#pragma unroll
        for (int mi = 0; mi < 2; ++mi)
#pragma unroll
            for (int ni = 0; ni < 4; ++ni)
#pragma unroll
                for (int q = 0; q < 4; ++q) c[mi][ni][q] = 0.f;

#pragma unroll 2
        for (int k0 = 0; k0 < 128; k0 += 8) {
            uint32_t a[2][4];
#pragma unroll
            for (int mi = 0; mi < 2; ++mi) {
                int r = ot + mi * 16 + gid;
                a[mi][0] = As[r * 132 + k0 + tig];
                a[mi][1] = As[(r + 8) * 132 + k0 + tig];
                a[mi][2] = As[r * 132 + k0 + 4 + tig];
                a[mi][3] = As[(r + 8) * 132 + k0 + 4 + tig];
            }
            uint32_t bf[4][2];
#pragma unroll
            for (int ni = 0; ni < 4; ++ni) {
                int nn = nt + ni * 8 + gid;
                bf[ni][0] = Bs[(k0 + tig) * 72 + nn];
                bf[ni][1] = Bs[(k0 + 4 + tig) * 72 + nn];
            }
#pragma unroll
            for (int mi = 0; mi < 2; ++mi)
#pragma unroll
                for (int ni = 0; ni < 4; ++ni)
                    mma_tf32(c[mi][ni], a[mi], bf[ni]);
        }

        // ---- epilogue: write D tiles to Ydst planes ----
        size_t dbase = ((size_t)plane * 2048 + (size_t)b * 64) * 128 + mh * 64;
#pragma unroll
        for (int mi = 0; mi < 2; ++mi) {
            int o = obase + mi * 16 + gid;
#pragma unroll
            for (int ni = 0; ni < 4; ++ni) {
                int m = nt + ni * 8 + 2 * tig;
                *(float2*)(Ydst + dbase + (size_t)o * 128 + m) =
                    make_float2(c[mi][ni][0], c[mi][ni][1]);
                *(float2*)(Ydst + dbase + (size_t)(o + 8) * 128 + m) =
                    make_float2(c[mi][ni][2], c[mi][ni][3]);
            }
        }
        __syncthreads();
    }
}

// ---------------------------------------------------------------------------
// K3a: inverse DFT, width branch (writes out). Block = (b*o, m-half).
__global__ __launch_bounds__(256, 3) void k_inv0(float* __restrict__ out) {
    extern __shared__ float sm[];
    float* As = sm;            // [64 s][68]
    float* Ci = As + 64 * 68;  // [32][64]
    float* Si = Ci + 2048;
    float* Pi = Si + 2048;

    int tid = threadIdx.x;
    int bx = blockIdx.x;
    int bo = bx >> 1, mh = bx & 1;
#pragma unroll
    for (int l = 0; l < 4; ++l) {
        int v = tid + l * 256;
        int s = v >> 4, c4 = (v & 15) << 2;
        *(float4*)(As + s * 68 + c4) =
            *(const float4*)(g_Yp + ((size_t)s * 2048 + bo) * 128 + mh * 64 + c4);
    }
#pragma unroll
    for (int l = 0; l < 8; ++l) {
        int v = tid + l * 256;
        Ci[v] = g_cI[v]; Si[v] = g_sI[v];
    }
    if (tid < 32) Pi[tid] = g_pI[tid];
    __syncthreads();

    int tx = tid & 15, ty = tid >> 4;
    int n0 = tx * 4, m0l = ty * 4;
    float ac[4][4] = {}, as_[4][4] = {}, ae[4] = {};
#pragma unroll 4
    for (int f = 0; f < 32; ++f) {
        float4 a4 = *(float4*)(As + (2 * f) * 68 + m0l);
        float4 b4 = *(float4*)(As + (2 * f + 1) * 68 + m0l);
        float4 c4v = *(float4*)(Ci + f * 64 + n0);
        float4 s4v = *(float4*)(Si + f * 64 + n0);
        float av[4] = {a4.x, a4.y, a4.z, a4.w};
        float bv[4] = {b4.x, b4.y, b4.z, b4.w};
        float cb[4] = {c4v.x, c4v.y, c4v.z, c4v.w};
        float sb[4] = {s4v.x, s4v.y, s4v.z, s4v.w};
        float pf = Pi[f];
#pragma unroll
        for (int j = 0; j < 4; ++j) {
#pragma unroll
            for (int c = 0; c < 4; ++c) {
                ac[j][c]  += av[j] * cb[c];
                as_[j][c] += bv[j] * sb[c];
            }
            ae[j] += av[j] * pf;
        }
    }
    float* op = out + (size_t)bo * 16384;
#pragma unroll
    for (int j = 0; j < 4; ++j) {
        int m = mh * 64 + m0l + j;
        *(float4*)(op + m * 128 + n0) =
            make_float4(ac[j][0] + as_[j][0], ac[j][1] + as_[j][1],
                        ac[j][2] + as_[j][2], ac[j][3] + as_[j][3]);
#pragma unroll
        for (int c = 0; c < 4; ++c) {
            int n = n0 + c;
            if (n > 0) op[m * 128 + 128 - n] = ac[j][c] - as_[j][c];
        }
        if (tx == 0) op[m * 128 + 64] = ae[j];
    }
}

// K3b: inverse DFT, height branch (accumulates into out). Block = (b*o, n-half).
__global__ __launch_bounds__(256, 3) void k_inv1(float* __restrict__ out) {
    extern __shared__ float sm[];
    float* As = sm;            // [64 s][68]
    float* Ci = As + 64 * 68;
    float* Si = Ci + 2048;
    float* Pi = Si + 2048;

    int tid = threadIdx.x;
    int bx = blockIdx.x;
    int bo = bx >> 1, nh = bx & 1;
#pragma unroll
    for (int l = 0; l < 4; ++l) {
        int v = tid + l * 256;
        int s = v >> 4, c4 = (v & 15) << 2;
        *(float4*)(As + s * 68 + c4) =
            *(const float4*)(g_Yp2 + ((size_t)s * 2048 + bo) * 128 + nh * 64 + c4);
    }
#pragma unroll
    for (int l = 0; l < 8; ++l) {
        int v = tid + l * 256;
        Ci[v] = g_cI[v]; Si[v] = g_sI[v];
    }
    if (tid < 32) Pi[tid] = g_pI[tid];
    __syncthreads();

    int tx = tid & 15, ty = tid >> 4;
    int n0l = tx * 4, m0 = ty * 4;
    float ac[4][4] = {}, as_[4][4] = {}, ae[4] = {};
#pragma unroll 4
    for (int f = 0; f < 32; ++f) {
        float4 a4 = *(float4*)(As + (2 * f) * 68 + n0l);
        float4 b4 = *(float4*)(As + (2 * f + 1) * 68 + n0l);
        float4 c4v = *(float4*)(Ci + f * 64 + m0);
        float4 s4v = *(float4*)(Si + f * 64 + m0);
        float av[4] = {a4.x, a4.y, a4.z, a4.w};
        float bv[4] = {b4.x, b4.y, b4.z, b4.w};
        float cc[4] = {c4v.x, c4v.y, c4v.z, c4v.w};
        float ss[4] = {s4v.x, s4v.y, s4v.z, s4v.w};
        float pf = Pi[f];
#pragma unroll
        for (int j = 0; j < 4; ++j)
#pragma unroll
            for (int c = 0; c < 4; ++c) {
                ac[j][c]  += cc[j] * av[c];
                as_[j][c] += ss[j] * bv[c];
            }
#pragma unroll
        for (int c = 0; c < 4; ++c) ae[c] += av[c] * pf;
    }
    float* op = out + (size_t)bo * 16384;
    int n0 = nh * 64 + n0l;
#pragma unroll
    for (int j = 0; j < 4; ++j) {
        int m = m0 + j;
        {
            float4 t = *(float4*)(op + m * 128 + n0);
            t.x += ac[j][0] + as_[j][0]; t.y += ac[j][1] + as_[j][1];
            t.z += ac[j][2] + as_[j][2]; t.w += ac[j][3] + as_[j][3];
            *(float4*)(op + m * 128 + n0) = t;
        }
        if (m > 0) {
            float4 t = *(float4*)(op + (128 - m) * 128 + n0);
            t.x += ac[j][0] - as_[j][0]; t.y += ac[j][1] - as_[j][1];
            t.z += ac[j][2] - as_[j][2]; t.w += ac[j][3] - as_[j][3];
            *(float4*)(op + (128 - m) * 128 + n0) = t;
        }
    }
    if (ty == 0) {
        float4 t = *(float4*)(op + 64 * 128 + n0);
        t.x += ae[0]; t.y += ae[1]; t.z += ae[2]; t.w += ae[3];
        *(float4*)(op + 64 * 128 + n0) = t;
    }
}

// ---------------------------------------------------------------------------
extern "C" void kernel_launch(void* const* d_in, const int* in_sizes, int n_in,
                              void* d_out, int out_size) {
    const float* x  = (const float*)d_in[0];
    const float* w0 = (const float*)d_in[1];
    const float* w1 = (const float*)d_in[2];
    float* out = (float*)d_out;
    (void)in_sizes; (void)n_in; (void)out_size;

    const int SMEM_FWD = (17028 + 2 * 2048 + 32) * 4;    // 84624
    const int SMEM_MIX = (128 * 132 + 128 * 72) * 4;     // 104448
    const int SMEM_INV = (64 * 68 + 2 * 2048 + 32) * 4;  // 33920

    cudaFuncSetAttribute(k_fwd,     cudaFuncAttributeMaxDynamicSharedMemorySize, SMEM_FWD);
    cudaFuncSetAttribute(k_mix_mma, cudaFuncAttributeMaxDynamicSharedMemorySize, SMEM_MIX);
    cudaFuncSetAttribute(k_inv0,    cudaFuncAttributeMaxDynamicSharedMemorySize, SMEM_INV);
    cudaFuncSetAttribute(k_inv1,    cudaFuncAttributeMaxDynamicSharedMemorySize, SMEM_INV);

    k_init   <<<4129, 256>>>(w0, w1);
    k_fwd    <<<2048, 256, SMEM_FWD>>>(x);    // both branches' spectra
    k_mix_mma<<<1024, 256, SMEM_MIX>>>();     // both branches' mix (tf32 mma)
    k_inv0   <<<4096, 256, SMEM_INV>>>(out);  // width branch -> out
    k_inv1   <<<4096, 256, SMEM_INV>>>(out);  // height branch += out
}

// round 17
// speedup vs baseline: 1.8603x; 1.1383x over previous
#include <cuda_runtime.h>
#include <cstdint>

// FactorizedSpectralConv2d: x[32,64,128,128] f32, w0/w1[64,64,32,2] f32.
// out = irfft_n(trunc32(rfft_n(x)) @ w0) + irfft_m(trunc32(rfft_m(x)) @ w1)
// Forward DFT + channel mix on tf32 mma.sync; inverse DFT SIMT fp32.
// One tf32 smem x-tile serves both fwd branches (as B k-major and as A row-major).

#define SQI 0.08838834764831843f   // 1/sqrt(128)

// ---- device-global scratch ----
__device__ float g_FxSM[64 * 128];        // [s][m] fwd basis, row-major A (branch X)
__device__ float g_FyKS[128 * 64];        // [n][s] fwd basis, k-major B (branch Y)
__device__ float g_cI[32 * 64];           // [f][n]  cf*cos
__device__ float g_sI[32 * 64];           // [f][n] -cf*sin
__device__ float g_pI[32];                // cf*(-1)^f
__device__ float g_Wmix[2 * 32 * 128 * 128]; // [branch][f][o2][i2] mix operand A
__device__ float g_Xf [64 * 32 * 64 * 128];  // branch Y spectra [s][b][i][m]
__device__ float g_Xf2[64 * 32 * 64 * 128];  // branch X spectra [s][b][i][n]
__device__ float g_Yp [64 * 32 * 64 * 128];  // branch Y mixed   [s][b][o][m]
__device__ float g_Yp2[64 * 32 * 64 * 128];  // branch X mixed   [s][b][o][n]

__device__ __forceinline__ uint32_t f2tf(float f) {
    uint32_t r;
    asm("cvt.rna.tf32.f32 %0, %1;" : "=r"(r) : "f"(f));
    return r;
}

__device__ __forceinline__ void mma_tf32(float* c, const uint32_t* a, const uint32_t* b) {
    asm volatile(
        "mma.sync.aligned.m16n8k8.row.col.f32.tf32.tf32.f32 "
        "{%0,%1,%2,%3}, {%4,%5,%6,%7}, {%8,%9}, {%0,%1,%2,%3};"
        : "+f"(c[0]), "+f"(c[1]), "+f"(c[2]), "+f"(c[3])
        : "r"(a[0]), "r"(a[1]), "r"(a[2]), "r"(a[3]), "r"(b[0]), "r"(b[1]));
}

// ---------------------------------------------------------------------------
// K0: dense fwd DFT bases + inv bases + mix operand A = [[Wr,-Wi],[Wi,Wr]].
__global__ __launch_bounds__(256) void k_init(const float* __restrict__ w0,
                                              const float* __restrict__ w1) {
    int idx = blockIdx.x * 256 + threadIdx.x;
    if (idx < 8192) {                    // FxSM: s=idx>>7, m=idx&127
        int s = idx >> 7, m = idx & 127;
        int f = s >> 1, c = s & 1;
        int t = (f * m) & 127;
        float sp, cp;
        sincospif((float)t * (1.0f / 64.0f), &sp, &cp);
        g_FxSM[idx] = c ? (-SQI * sp) : (SQI * cp);
    } else if (idx < 16384) {            // FyKS: n=q>>6, s=q&63
        int q = idx - 8192;
        int n = q >> 6, s = q & 63;
        int f = s >> 1, c = s & 1;
        int t = (f * n) & 127;
        float sp, cp;
        sincospif((float)t * (1.0f / 64.0f), &sp, &cp);
        g_FyKS[q] = c ? (-SQI * sp) : (SQI * cp);
    } else if (idx < 18432) {            // cI
        int q = idx - 16384;
        int f = q >> 6, n = q & 63;
        int t = (f * n) & 127;
        float cf = (f == 0) ? SQI : (2.0f * SQI);
        g_cI[q] = cf * cospif((float)t * (1.0f / 64.0f));
    } else if (idx < 20480) {            // sI
        int q = idx - 18432;
        int f = q >> 6, n = q & 63;
        int t = (f * n) & 127;
        float cf = (f == 0) ? SQI : (2.0f * SQI);
        g_sI[q] = -cf * sinpif((float)t * (1.0f / 64.0f));
    } else if (idx < 20512) {            // pI
        int f = idx - 20480;
        float cf = (f == 0) ? SQI : (2.0f * SQI);
        g_pI[f] = (f & 1) ? -cf : cf;
    } else if (idx < 20512 + 2 * 32 * 128 * 128) {  // g_Wmix
        int q = idx - 20512;
        int branch = q >> 19;
        int r = q & 524287;
        int f = r >> 14, o2 = (r >> 7) & 127, i2 = r & 127;
        int i = i2 & 63, o = o2 & 63;
        const float* w = branch ? w1 : w0;
        int base = ((i * 64 + o) * 32 + f) * 2;
        float v;
        if (o2 < 64)  v = (i2 < 64) ?  w[base + 0] : -w[base + 1];
        else          v = (i2 < 64) ?  w[base + 1] :  w[base + 0];
        g_Wmix[q] = v;
    }
}

// ---------------------------------------------------------------------------
// K1: forward DFT, both branches, tf32 mma. Block = one (b,i), 256 threads.
// Xs[128][132] tf32 serves as B (k-major over m) for branch X and as A
// (row-major over m, k=n) for branch Y. No transpose needed.
__global__ __launch_bounds__(256) void k_fwd_mma(const float* __restrict__ x) {
    extern __shared__ float smf[];
    uint32_t* Xs = (uint32_t*)smf;        // [128][132]
    uint32_t* Ax = Xs + 128 * 132;        // [64][132]  FxT (branch X A)
    uint32_t* By = Ax + 64 * 132;         // [128][72]  Fy  (branch Y B)

    int tid = threadIdx.x, bi = blockIdx.x;
    const float* xr = x + (size_t)bi * 16384;
#pragma unroll
    for (int l = 0; l < 16; ++l) {
        int v = tid + l * 256;
        int row = v >> 5, c4 = (v & 31) << 2;
        float4 d = *(const float4*)(xr + row * 128 + c4);
        *(uint4*)(Xs + row * 132 + c4) =
            make_uint4(f2tf(d.x), f2tf(d.y), f2tf(d.z), f2tf(d.w));
    }
#pragma unroll
    for (int l = 0; l < 8; ++l) {
        int v = tid + l * 256;
        int row = v >> 5, c4 = (v & 31) << 2;
        float4 d = *(const float4*)(g_FxSM + row * 128 + c4);
        *(uint4*)(Ax + row * 132 + c4) =
            make_uint4(f2tf(d.x), f2tf(d.y), f2tf(d.z), f2tf(d.w));
    }
#pragma unroll
    for (int l = 0; l < 8; ++l) {
        int v = tid + l * 256;
        int row = v >> 4, c4 = (v & 15) << 2;
        float4 d = *(const float4*)(g_FyKS + row * 64 + c4);
        *(uint4*)(By + row * 72 + c4) =
            make_uint4(f2tf(d.x), f2tf(d.y), f2tf(d.z), f2tf(d.w));
    }
    __syncthreads();

    int lane = tid & 31, wid = tid >> 5, gid = lane >> 2, tig = lane & 3;

    // ---- branch X: D[s=64][n=128] = FxT[64][128m] x X[m][n] ----
    {
        int ws = (wid & 1) * 32, wn = (wid >> 1) * 32;
        float c[2][4][4] = {};
#pragma unroll 2
        for (int k0 = 0; k0 < 128; k0 += 8) {
            uint32_t a[2][4], b[4][2];
#pragma unroll
            for (int mi = 0; mi < 2; ++mi) {
                int r = ws + mi * 16 + gid;
                a[mi][0] = Ax[r * 132 + k0 + tig];
                a[mi][1] = Ax[(r + 8) * 132 + k0 + tig];
                a[mi][2] = Ax[r * 132 + k0 + 4 + tig];
                a[mi][3] = Ax[(r + 8) * 132 + k0 + 4 + tig];
            }
#pragma unroll
            for (int ni = 0; ni < 4; ++ni) {
                int nn = wn + ni * 8 + gid;
                b[ni][0] = Xs[(k0 + tig) * 132 + nn];
                b[ni][1] = Xs[(k0 + 4 + tig) * 132 + nn];
            }
#pragma unroll
            for (int mi = 0; mi < 2; ++mi)
#pragma unroll
                for (int ni = 0; ni < 4; ++ni) mma_tf32(c[mi][ni], a[mi], b[ni]);
        }
#pragma unroll
        for (int mi = 0; mi < 2; ++mi) {
            int s = ws + mi * 16 + gid;
#pragma unroll
            for (int ni = 0; ni < 4; ++ni) {
                int n = wn + ni * 8 + 2 * tig;
                *(float2*)(g_Xf2 + ((size_t)s * 2048 + bi) * 128 + n) =
                    make_float2(c[mi][ni][0], c[mi][ni][1]);
                *(float2*)(g_Xf2 + ((size_t)(s + 8) * 2048 + bi) * 128 + n) =
                    make_float2(c[mi][ni][2], c[mi][ni][3]);
            }
        }
    }

    // ---- branch Y: D[m=128][s=64] = X[m][n] x Fy[n][s], transposed store ----
    {
        int wm = (wid & 3) * 32, ws = (wid >> 2) * 32;
        float c[2][4][4] = {};
#pragma unroll 2
        for (int k0 = 0; k0 < 128; k0 += 8) {
            uint32_t a[2][4], b[4][2];
#pragma unroll
            for (int mi = 0; mi < 2; ++mi) {
                int r = wm + mi * 16 + gid;
                a[mi][0] = Xs[r * 132 + k0 + tig];
                a[mi][1] = Xs[(r + 8) * 132 + k0 + tig];
                a[mi][2] = Xs[r * 132 + k0 + 4 + tig];
                a[mi][3] = Xs[(r + 8) * 132 + k0 + 4 + tig];
            }
#pragma unroll
            for (int ni = 0; ni < 4; ++ni) {
                int nn = ws + ni * 8 + gid;
                b[ni][0] = By[(k0 + tig) * 72 + nn];
                b[ni][1] = By[(k0 + 4 + tig) * 72 + nn];
            }
#pragma unroll
            for (int mi = 0; mi < 2; ++mi)
#pragma unroll
                for (int ni = 0; ni < 4; ++ni) mma_tf32(c[mi][ni], a[mi], b[ni]);
        }
#pragma unroll
        for (int mi = 0; mi < 2; ++mi) {
            int m = wm + mi * 16 + gid;
#pragma unroll
            for (int ni = 0; ni < 4; ++ni) {
                int s = ws + ni * 8 + 2 * tig;
                g_Xf[((size_t)s * 2048 + bi) * 128 + m]           = c[mi][ni][0];
                g_Xf[((size_t)(s + 1) * 2048 + bi) * 128 + m]     = c[mi][ni][1];
                g_Xf[((size_t)s * 2048 + bi) * 128 + m + 8]       = c[mi][ni][2];
                g_Xf[((size_t)(s + 1) * 2048 + bi) * 128 + m + 8] = c[mi][ni][3];
            }
        }
    }
}

// ---------------------------------------------------------------------------
// K2: channel mix on tf32 mma.sync. 1024 blocks: bg3|mh1|f5|branch1.
__global__ __launch_bounds__(256) void k_mix_mma() {
    extern __shared__ float smf[];
    uint32_t* As = (uint32_t*)smf;            // [128][132] tf32
    uint32_t* Bs = As + 128 * 132;            // [128][72]  tf32

    int tid = threadIdx.x;
    int bx = blockIdx.x;
    int bg = bx & 7, mh = (bx >> 3) & 1, f = (bx >> 4) & 31, branch = bx >> 9;

    const float* Ap = g_Wmix + (((size_t)branch * 32 + f) << 14);
    const float* Xsrc = branch ? g_Xf2 : g_Xf;
    float* Ydst = branch ? g_Yp2 : g_Yp;

    // ---- A fill once (fp32 -> tf32) ----
#pragma unroll
    for (int l = 0; l < 16; ++l) {
        int v = tid + l * 256;
        int o2 = v >> 5, c4 = (v & 31) << 2;
        float4 d = *(const float4*)(Ap + o2 * 128 + c4);
        uint4 t = make_uint4(f2tf(d.x), f2tf(d.y), f2tf(d.z), f2tf(d.w));
        *(uint4*)(As + o2 * 132 + c4) = t;
    }

    int lane = tid & 31, wid = tid >> 5;
    int gid = lane >> 2, tig = lane & 3;
    int ot = (wid & 3) * 32;          // o2 tile base
    int nt = (wid >> 2) * 32;         // m tile base
    int plane = 2 * f + (ot >> 6);    // const per warp
    int obase = ot & 63;

    for (int bb = 0; bb < 4; ++bb) {
        int b = bg * 4 + bb;
        // ---- B fill (fp32 -> tf32) ----
        size_t xb = ((size_t)(2 * f) * 2048 + (size_t)b * 64) * 128 + mh * 64;
#pragma unroll
        for (int l = 0; l < 8; ++l) {
            int v = tid + l * 256;
            int i2 = v >> 4, c4 = (v & 15) << 2;
            const float* src = Xsrc + xb + (size_t)(i2 >> 6) * 262144 + (i2 & 63) * 128 + c4;
            float4 d = *(const float4*)src;
            uint4 t = make_uint4(f2tf(d.x), f2tf(d.y), f2tf(d.z), f2tf(d.w));
            *(uint4*)(Bs + i2 * 72 + c4) = t;
        }
        __syncthreads();

        float c[2][4][4];
#pragma unroll
        for (int mi = 0; mi < 2; ++mi)
#pragma unroll
            for (int ni = 0; ni < 4; ++ni)
#pragma unroll
                for (int q = 0; q < 4; ++q) c[mi][ni][q] = 0.f;

#pragma unroll 2
        for (int k0 = 0; k0 < 128; k0 += 8) {
            uint32_t a[2][4];
#pragma unroll
            for (int mi = 0; mi < 2; ++mi) {
                int r = ot + mi * 16 + gid;
                a[mi][0] = As[r * 132 + k0 + tig];
                a[mi][1] = As[(r + 8) * 132 + k0 + tig];
                a[mi][2] = As[r * 132 + k0 + 4 + tig];
                a[mi][3] = As[(r + 8) * 132 + k0 + 4 + tig];
            }
            uint32_t bf[4][2];
#pragma unroll
            for (int ni = 0; ni < 4; ++ni) {
                int nn = nt + ni * 8 + gid;
                bf[ni][0] = Bs[(k0 + tig) * 72 + nn];
                bf[ni][1] = Bs[(k0 + 4 + tig) * 72 + nn];
            }
#pragma unroll
            for (int mi = 0; mi < 2; ++mi)
#pragma unroll
                for (int ni = 0; ni < 4; ++ni)
                    mma_tf32(c[mi][ni], a[mi], bf[ni]);
        }

        // ---- epilogue: write D tiles to Ydst planes ----
        size_t dbase = ((size_t)plane * 2048 + (size_t)b * 64) * 128 + mh * 64;
#pragma unroll
        for (int mi = 0; mi < 2; ++mi) {
            int o = obase + mi * 16 + gid;
#pragma unroll
            for (int ni = 0; ni < 4; ++ni) {
                int m = nt + ni * 8 + 2 * tig;
                *(float2*)(Ydst + dbase + (size_t)o * 128 + m) =
                    make_float2(c[mi][ni][0], c[mi][ni][1]);
                *(float2*)(Ydst + dbase + (size_t)(o + 8) * 128 + m) =
                    make_float2(c[mi][ni][2], c[mi][ni][3]);
            }
        }
        __syncthreads();
    }
}

// ---------------------------------------------------------------------------
// K3a: inverse DFT, width branch (writes out). Block = (b*o, m-half).
__global__ __launch_bounds__(256, 3) void k_inv0(float* __restrict__ out) {
    extern __shared__ float sm[];
    float* As = sm;            // [64 s][68]
    float* Ci = As + 64 * 68;  // [32][64]
    float* Si = Ci + 2048;
    float* Pi = Si + 2048;

    int tid = threadIdx.x;
    int bx = blockIdx.x;
    int bo = bx >> 1, mh = bx & 1;
#pragma unroll
    for (int l = 0; l < 4; ++l) {
        int v = tid + l * 256;
        int s = v >> 4, c4 = (v & 15) << 2;
        *(float4*)(As + s * 68 + c4) =
            *(const float4*)(g_Yp + ((size_t)s * 2048 + bo) * 128 + mh * 64 + c4);
    }
#pragma unroll
    for (int l = 0; l < 8; ++l) {
        int v = tid + l * 256;
        Ci[v] = g_cI[v]; Si[v] = g_sI[v];
    }
    if (tid < 32) Pi[tid] = g_pI[tid];
    __syncthreads();

    int tx = tid & 15, ty = tid >> 4;
    int n0 = tx * 4, m0l = ty * 4;
    float ac[4][4] = {}, as_[4][4] = {}, ae[4] = {};
#pragma unroll 4
    for (int f = 0; f < 32; ++f) {
        float4 a4 = *(float4*)(As + (2 * f) * 68 + m0l);
        float4 b4 = *(float4*)(As + (2 * f + 1) * 68 + m0l);
        float4 c4v = *(float4*)(Ci + f * 64 + n0);
        float4 s4v = *(float4*)(Si + f * 64 + n0);
        float av[4] = {a4.x, a4.y, a4.z, a4.w};
        float bv[4] = {b4.x, b4.y, b4.z, b4.w};
        float cb[4] = {c4v.x, c4v.y, c4v.z, c4v.w};
        float sb[4] = {s4v.x, s4v.y, s4v.z, s4v.w};
        float pf = Pi[f];
#pragma unroll
        for (int j = 0; j < 4; ++j) {
#pragma unroll
            for (int c = 0; c < 4; ++c) {
                ac[j][c]  += av[j] * cb[c];
                as_[j][c] += bv[j] * sb[c];
            }
            ae[j] += av[j] * pf;
        }
    }
    float* op = out + (size_t)bo * 16384;
#pragma unroll
    for (int j = 0; j < 4; ++j) {
        int m = mh * 64 + m0l + j;
        *(float4*)(op + m * 128 + n0) =
            make_float4(ac[j][0] + as_[j][0], ac[j][1] + as_[j][1],
                        ac[j][2] + as_[j][2], ac[j][3] + as_[j][3]);
#pragma unroll
        for (int c = 0; c < 4; ++c) {
            int n = n0 + c;
            if (n > 0) op[m * 128 + 128 - n] = ac[j][c] - as_[j][c];
        }
        if (tx == 0) op[m * 128 + 64] = ae[j];
    }
}

// K3b: inverse DFT, height branch (accumulates into out). Block = (b*o, n-half).
__global__ __launch_bounds__(256, 3) void k_inv1(float* __restrict__ out) {
    extern __shared__ float sm[];
    float* As = sm;            // [64 s][68]
    float* Ci = As + 64 * 68;
    float* Si = Ci + 2048;
    float* Pi = Si + 2048;

    int tid = threadIdx.x;
    int bx = blockIdx.x;
    int bo = bx >> 1, nh = bx & 1;
#pragma unroll
    for (int l = 0; l < 4; ++l) {
        int v = tid + l * 256;
        int s = v >> 4, c4 = (v & 15) << 2;
        *(float4*)(As + s * 68 + c4) =
            *(const float4*)(g_Yp2 + ((size_t)s * 2048 + bo) * 128 + nh * 64 + c4);
    }
#pragma unroll
    for (int l = 0; l < 8; ++l) {
        int v = tid + l * 256;
        Ci[v] = g_cI[v]; Si[v] = g_sI[v];
    }
    if (tid < 32) Pi[tid] = g_pI[tid];
    __syncthreads();

    int tx = tid & 15, ty = tid >> 4;
    int n0l = tx * 4, m0 = ty * 4;
    float ac[4][4] = {}, as_[4][4] = {}, ae[4] = {};
#pragma unroll 4
    for (int f = 0; f < 32; ++f) {
        float4 a4 = *(float4*)(As + (2 * f) * 68 + n0l);
        float4 b4 = *(float4*)(As + (2 * f + 1) * 68 + n0l);
        float4 c4v = *(float4*)(Ci + f * 64 + m0);
        float4 s4v = *(float4*)(Si + f * 64 + m0);
        float av[4] = {a4.x, a4.y, a4.z, a4.w};
        float bv[4] = {b4.x, b4.y, b4.z, b4.w};
        float cc[4] = {c4v.x, c4v.y, c4v.z, c4v.w};
        float ss[4] = {s4v.x, s4v.y, s4v.z, s4v.w};
        float pf = Pi[f];
#pragma unroll
        for (int j = 0; j < 4; ++j)
#pragma unroll
            for (int c = 0; c < 4; ++c) {
                ac[j][c]  += cc[j] * av[c];
                as_[j][c] += ss[j] * bv[c];
            }
#pragma unroll
        for (int c = 0; c < 4; ++c) ae[c] += av[c] * pf;
    }
    float* op = out + (size_t)bo * 16384;
    int n0 = nh * 64 + n0l;
#pragma unroll
    for (int j = 0; j < 4; ++j) {
        int m = m0 + j;
        {
            float4 t = *(float4*)(op + m * 128 + n0);
            t.x += ac[j][0] + as_[j][0]; t.y += ac[j][1] + as_[j][1];
            t.z += ac[j][2] + as_[j][2]; t.w += ac[j][3] + as_[j][3];
            *(float4*)(op + m * 128 + n0) = t;
        }
        if (m > 0) {
            float4 t = *(float4*)(op + (128 - m) * 128 + n0);
            t.x += ac[j][0] - as_[j][0]; t.y += ac[j][1] - as_[j][1];
            t.z += ac[j][2] - as_[j][2]; t.w += ac[j][3] - as_[j][3];
            *(float4*)(op + (128 - m) * 128 + n0) = t;
        }
    }
    if (ty == 0) {
        float4 t = *(float4*)(op + 64 * 128 + n0);
        t.x += ae[0]; t.y += ae[1]; t.z += ae[2]; t.w += ae[3];
        *(float4*)(op + 64 * 128 + n0) = t;
    }
}

// ---------------------------------------------------------------------------
extern "C" void kernel_launch(void* const* d_in, const int* in_sizes, int n_in,
                              void* d_out, int out_size) {
    const float* x  = (const float*)d_in[0];
    const float* w0 = (const float*)d_in[1];
    const float* w1 = (const float*)d_in[2];
    float* out = (float*)d_out;
    (void)in_sizes; (void)n_in; (void)out_size;

    const int SMEM_FWD = (128 * 132 + 64 * 132 + 128 * 72) * 4;  // 138240
    const int SMEM_MIX = (128 * 132 + 128 * 72) * 4;             // 104448
    const int SMEM_INV = (64 * 68 + 2 * 2048 + 32) * 4;          // 33920

    cudaFuncSetAttribute(k_fwd_mma, cudaFuncAttributeMaxDynamicSharedMemorySize, SMEM_FWD);
    cudaFuncSetAttribute(k_mix_mma, cudaFuncAttributeMaxDynamicSharedMemorySize, SMEM_MIX);
    cudaFuncSetAttribute(k_inv0,    cudaFuncAttributeMaxDynamicSharedMemorySize, SMEM_INV);
    cudaFuncSetAttribute(k_inv1,    cudaFuncAttributeMaxDynamicSharedMemorySize, SMEM_INV);

    k_init   <<<4177, 256>>>(w0, w1);
    k_fwd_mma<<<2048, 256, SMEM_FWD>>>(x);    // both branches' spectra (tf32 mma)
    k_mix_mma<<<1024, 256, SMEM_MIX>>>();     // both branches' mix (tf32 mma)
    k_inv0   <<<4096, 256, SMEM_INV>>>(out);  // width branch -> out
    k_inv1   <<<4096, 256, SMEM_INV>>>(out);  // height branch += out
}